// round 3
// baseline (speedup 1.0000x reference)
#include <cuda_runtime.h>

// Problem constants
#define NNODE   200000
#define NDIM    128
#define HIDDEN  512
#define GDIM    128
#define NGRAPH  1024

// Tiling
#define TM      64          // nodes per CTA
#define HC      64          // hidden chunk
#define NCHUNK  (HIDDEN/HC) // 8
#define THREADS 256

#define XS_PITCH 68         // pad 256-row x tile: 68%32=4 -> <=4-way STS conflict, 16B aligned
#define HT_PITCH 68
#define RT_PITCH 132

// smem carve (floats)
#define SM_XST   (256 * XS_PITCH)   // 17408
#define SM_WC    16384              // [256][64] weight chunk (reused as RT 64x132=8448)
#define SM_HCT   (HC * HT_PITCH)    // 4352
#define SM_W2C   (HC * GDIM)        // 8192
#define SM_BB    64
#define SM_GSH   64
#define SM_FLOATS (SM_XST + SM_WC + SM_HCT + SM_W2C + SM_BB + SM_GSH)
#define SMEM_BYTES (SM_FLOATS * 4)  // 185856 B

// One 2-layer MLP pass: hidden = ReLU(X @ W1[:,chunk] + b1), o += hidden @ W2[chunk,:]
// X lives transposed in xsT[k][node]. Output o[4][8] = (4 nodes) x (8 of 128 cols) per thread.
template <int KD>
__device__ __forceinline__ void run_net(
    const float* __restrict__ W1, const float* __restrict__ b1,
    const float* __restrict__ W2,
    float* xsT, float* Wc, float* HcT, float* W2c, float* bb,
    float (&o)[4][8], int tid)
{
    const int tx = tid & 15;   // col group
    const int ty = tid >> 4;   // node group (4 nodes)

    #pragma unroll 1
    for (int ch = 0; ch < NCHUNK; ++ch) {
        const int c0 = ch * HC;
        __syncthreads();  // prev chunk fully consumed

        // stage W1 chunk: Wc[k][0..63] = W1[k][c0..c0+63], KD rows
        {
            const int nv = KD * HC / 4;  // float4 count
            for (int f = tid; f < nv; f += THREADS) {
                int row = f >> 4;
                int c4  = f & 15;
                ((float4*)Wc)[f] =
                    *(const float4*)&W1[row * HIDDEN + c0 + c4 * 4];
            }
        }
        // stage W2 chunk: rows [c0, c0+64) of [HIDDEN][GDIM], contiguous
        {
            const float4* src = (const float4*)(W2 + c0 * GDIM);
            for (int f = tid; f < HC * GDIM / 4; f += THREADS)
                ((float4*)W2c)[f] = src[f];
        }
        if (tid < HC) bb[tid] = b1[c0 + tid];
        __syncthreads();

        // ---- layer 1: c[node 4][col 4] over K=KD ----
        float c[4][4] = {};
        #pragma unroll 8
        for (int k = 0; k < KD; ++k) {
            float4 a = *(const float4*)&xsT[k * XS_PITCH + ty * 4];
            float4 b = *(const float4*)&Wc[k * HC + tx * 4];
            float av[4] = {a.x, a.y, a.z, a.w};
            float bv[4] = {b.x, b.y, b.z, b.w};
            #pragma unroll
            for (int i = 0; i < 4; ++i)
                #pragma unroll
                for (int j = 0; j < 4; ++j)
                    c[i][j] = fmaf(av[i], bv[j], c[i][j]);
        }

        // bias + ReLU -> HcT[hid][node]
        #pragma unroll
        for (int j = 0; j < 4; ++j) {
            float bj = bb[tx * 4 + j];
            #pragma unroll
            for (int i = 0; i < 4; ++i) {
                float v = c[i][j] + bj;
                HcT[(tx * 4 + j) * HT_PITCH + ty * 4 + i] = v > 0.f ? v : 0.f;
            }
        }
        __syncthreads();

        // ---- layer 2: o[4 nodes][8 cols] += HcT @ W2c ----
        #pragma unroll 4
        for (int kk = 0; kk < HC; ++kk) {
            float4 a  = *(const float4*)&HcT[kk * HT_PITCH + ty * 4];
            float4 b0 = *(const float4*)&W2c[kk * GDIM + tx * 8];
            float4 b1v= *(const float4*)&W2c[kk * GDIM + tx * 8 + 4];
            float av[4] = {a.x, a.y, a.z, a.w};
            float bv[8] = {b0.x, b0.y, b0.z, b0.w, b1v.x, b1v.y, b1v.z, b1v.w};
            #pragma unroll
            for (int i = 0; i < 4; ++i)
                #pragma unroll
                for (int j = 0; j < 8; ++j)
                    o[i][j] = fmaf(av[i], bv[j], o[i][j]);
        }
    }
}

__global__ __launch_bounds__(THREADS, 1)
void readout_fused_kernel(
    const float* __restrict__ h_T, const float* __restrict__ h_0,
    const int* __restrict__ graph_index,     // JAX x64-disabled: int64 -> int32 on disk
    const float* __restrict__ Wi1, const float* __restrict__ bi1,
    const float* __restrict__ Wi2, const float* __restrict__ bi2,
    const float* __restrict__ Wj1, const float* __restrict__ bj1,
    const float* __restrict__ Wj2, const float* __restrict__ bj2,
    float* __restrict__ R)
{
    extern __shared__ float sm[];
    float* xsT = sm;
    float* Wc  = xsT + SM_XST;
    float* HcT = Wc + SM_WC;
    float* W2c = HcT + SM_HCT;
    float* bb  = W2c + SM_W2C;
    int*   gsh = (int*)(bb + SM_BB);
    float* RT  = Wc;   // reused after last layer-1

    const int tid = threadIdx.x;
    const int m0  = blockIdx.x * TM;

    if (tid < TM) {
        int g = graph_index[m0 + tid];
        g = g < 0 ? 0 : (g >= NGRAPH ? NGRAPH - 1 : g);  // safety clamp (no-op if in range)
        gsh[tid] = g;
    }

    // stage xsT[k][node] = concat(h_T, h_0): coalesced global reads (k = tid)
    {
        const int k = tid;
        const float* src = (k < NDIM) ? (h_T + k) : (h_0 + (k - NDIM));
        #pragma unroll 4
        for (int i = 0; i < TM; ++i)
            xsT[k * XS_PITCH + i] = src[(m0 + i) * NDIM];
    }
    __syncthreads();

    float oi[4][8] = {};
    float oj[4][8] = {};

    run_net<2 * NDIM>(Wi1, bi1, Wi2, xsT, Wc, HcT, W2c, bb, oi, tid); // i-net K=256
    run_net<NDIM>    (Wj1, bj1, Wj2, xsT, Wc, HcT, W2c, bb, oj, tid); // j-net K=128

    // epilogue: R_v = sigmoid(oi + bi2) * (oj + bj2) -> RT[node][col]
    {
        const int tx = tid & 15;
        const int ty = tid >> 4;
        #pragma unroll
        for (int j = 0; j < 8; ++j) {
            int col = tx * 8 + j;
            float bgi = __ldg(&bi2[col]);
            float bgj = __ldg(&bj2[col]);
            #pragma unroll
            for (int i = 0; i < 4; ++i) {
                int node = ty * 4 + i;
                float g = 1.f / (1.f + __expf(-(oi[i][j] + bgi)));
                float v = oj[i][j] + bgj;
                RT[node * RT_PITCH + col] = g * v;
            }
        }
    }
    __syncthreads();

    // segment-sum (graph_index is sorted): one thread per output column,
    // serial scan over 64 nodes, atomic per segment boundary (~1.3/tile).
    if (tid < GDIM) {
        const int c = tid;
        float sum = 0.f;
        int gp = gsh[0];
        #pragma unroll 4
        for (int i = 0; i < TM; ++i) {
            int g = gsh[i];
            if (g != gp) {
                atomicAdd(&R[gp * GDIM + c], sum);
                sum = 0.f;
                gp = g;
            }
            sum += RT[i * RT_PITCH + c];
        }
        atomicAdd(&R[gp * GDIM + c], sum);
    }
}

__global__ void zero_out_kernel(float* __restrict__ R, int n)
{
    int i = blockIdx.x * blockDim.x + threadIdx.x;
    if (i < n) R[i] = 0.f;
}

extern "C" void kernel_launch(void* const* d_in, const int* in_sizes, int n_in,
                              void* d_out, int out_size)
{
    (void)in_sizes; (void)n_in; (void)out_size;
    const float* h_T  = (const float*)d_in[0];
    const float* h_0  = (const float*)d_in[1];
    const int*   gidx = (const int*)d_in[2];
    const float* Wi1  = (const float*)d_in[3];
    const float* bi1  = (const float*)d_in[4];
    const float* Wi2  = (const float*)d_in[5];
    const float* bi2  = (const float*)d_in[6];
    const float* Wj1  = (const float*)d_in[7];
    const float* bj1  = (const float*)d_in[8];
    const float* Wj2  = (const float*)d_in[9];
    const float* bj2  = (const float*)d_in[10];
    float* R = (float*)d_out;

    cudaFuncSetAttribute(readout_fused_kernel,
                         cudaFuncAttributeMaxDynamicSharedMemorySize, SMEM_BYTES);

    zero_out_kernel<<<(NGRAPH * GDIM + 255) / 256, 256>>>(R, NGRAPH * GDIM);
    readout_fused_kernel<<<NNODE / TM, THREADS, SMEM_BYTES>>>(
        h_T, h_0, gidx, Wi1, bi1, Wi2, bi2, Wj1, bj1, Wj2, bj2, R);
}

// round 7
// speedup vs baseline: 6.8689x; 6.8689x over previous
#include <cuda_runtime.h>
#include <cuda_fp16.h>
#include <cstdint>

#define NNODE   200000
#define NDIM    128
#define HIDDEN  512
#define GDIM    128
#define NGRAPH  1024

#define TM      128
#define THREADS 256
#define NTILES  ((NNODE + TM - 1) / TM)   // 1563
#define NCH     8                          // hidden chunks of 64

// smem pitches (in half elements); all row strides ≡ 4 words mod 32 -> conflict-free ldmatrix
#define XP   264     // X  [128][264]
#define W1P  264     // W1i chunk [64][264] (K=256)
#define W1JP 136     // W1j chunk [64][136] (K=128)
#define W2P  72      // W2 chunk [128][72]  (K=64)
#define HP   72      // H  [128][72]
#define RTP  132     // RT [128][132] f32

// smem byte offsets
#define SX    0                        // 128*264*2 = 67584 (reused as RT: 128*132*4 = 67584)
#define SW    67584                    // WBuf: W1i(33792)+W1j(17408)=51200 ; or W2i(18432)+W2j(18432)
#define SW1J  (SW + 33792)
#define SW2I  SW
#define SW2J  (SW + 18432)
#define SH    118784                   // Hi 18432
#define SHJ   (SH + 18432)             // Hj 18432
#define SG    155648                   // gsh 128 ints
#define SMEM_BYTES 156672

// prepped fp16 weights, n-major [n][k] with padded pitch
__device__ __align__(16) __half g_W1i[HIDDEN * 264];   // [512][264], k<256 valid
__device__ __align__(16) __half g_W1j[HIDDEN * 136];   // [512][136], k<128 valid
__device__ __align__(16) __half g_W2i[GDIM * 520];     // [128][520], k<512 valid
__device__ __align__(16) __half g_W2j[GDIM * 520];

// ---------------- PTX helpers ----------------
__device__ __forceinline__ uint32_t smem_u32(const void* p) {
    uint32_t a;
    asm("{ .reg .u64 t; cvta.to.shared.u64 t, %1; cvt.u32.u64 %0, t; }" : "=r"(a) : "l"(p));
    return a;
}
__device__ __forceinline__ void ldm4(uint32_t* r, uint32_t addr) {
    asm volatile("ldmatrix.sync.aligned.m8n8.x4.shared.b16 {%0,%1,%2,%3}, [%4];"
                 : "=r"(r[0]), "=r"(r[1]), "=r"(r[2]), "=r"(r[3]) : "r"(addr));
}
__device__ __forceinline__ void mma16816(float* d, const uint32_t* a, uint32_t b0, uint32_t b1) {
    asm volatile("mma.sync.aligned.m16n8k16.row.col.f32.f16.f16.f32 "
                 "{%0,%1,%2,%3}, {%4,%5,%6,%7}, {%8,%9}, {%0,%1,%2,%3};"
                 : "+f"(d[0]), "+f"(d[1]), "+f"(d[2]), "+f"(d[3])
                 : "r"(a[0]), "r"(a[1]), "r"(a[2]), "r"(a[3]), "r"(b0), "r"(b1));
}

// ---------------- prep kernels (run each launch; tiny) ----------------
__global__ void prep_w1_kernel(const float* __restrict__ Wi1, const float* __restrict__ Wj1)
{
    int idx = blockIdx.x * blockDim.x + threadIdx.x;
    const int NI = HIDDEN * 256;           // Wi1: [256 k][512 n]
    const int NJ = HIDDEN * 128;           // Wj1: [128 k][512 n]
    if (idx < NI) {
        int n = idx >> 8, k = idx & 255;
        g_W1i[n * 264 + k] = __float2half_rn(Wi1[k * HIDDEN + n]);
    } else if (idx < NI + NJ) {
        int t = idx - NI;
        int n = t >> 7, k = t & 127;
        g_W1j[n * 136 + k] = __float2half_rn(Wj1[k * HIDDEN + n]);
    }
}
__global__ void prep_w2_kernel(const float* __restrict__ Wi2, const float* __restrict__ Wj2)
{
    int idx = blockIdx.x * blockDim.x + threadIdx.x;   // over 2 * 512 * 128
    const int NT = HIDDEN * GDIM;
    if (idx >= 2 * NT) return;
    int net = idx >= NT;
    int t = net ? idx - NT : idx;
    int k = t >> 7, n = t & 127;           // W2: [512 k][128 n]
    __half v = __float2half_rn((net ? Wj2 : Wi2)[k * GDIM + n]);
    if (net) g_W2j[n * 520 + k] = v;
    else     g_W2i[n * 520 + k] = v;
}

__global__ void zero_out_kernel(float* __restrict__ R, int n)
{
    int i = blockIdx.x * blockDim.x + threadIdx.x;
    if (i < n) R[i] = 0.f;
}

// stage R rows x C halves (C%8==0) from global [srcPitch] to smem [dstPitch], uint4 copies
template <int RWS, int CQ, int SP, int DP>
__device__ __forceinline__ void stage_tile(__half* dst, const __half* __restrict__ src, int tid)
{
    const int nq = RWS * CQ;
    #pragma unroll 4
    for (int f = tid; f < nq; f += THREADS) {
        int row = f / CQ, q = f - row * CQ;
        *(uint4*)(dst + row * DP + q * 8) = *(const uint4*)(src + row * SP + q * 8);
    }
}

// ---------------- main kernel ----------------
__global__ __launch_bounds__(THREADS, 1)
void readout_mma_kernel(
    const float* __restrict__ h_T, const float* __restrict__ h_0,
    const int* __restrict__ graph_index,
    const float* __restrict__ bi1, const float* __restrict__ bi2,
    const float* __restrict__ bj1, const float* __restrict__ bj2,
    float* __restrict__ R)
{
    extern __shared__ __align__(16) char sm[];
    __half* Xs  = (__half*)(sm + SX);
    __half* W1i = (__half*)(sm + SW);
    __half* W1j = (__half*)(sm + SW1J);
    __half* W2i = (__half*)(sm + SW2I);
    __half* W2j = (__half*)(sm + SW2J);
    __half* Hi  = (__half*)(sm + SH);
    __half* Hj  = (__half*)(sm + SHJ);
    int*    gsh = (int*)(sm + SG);
    float*  RT  = (float*)(sm + SX);

    const int tid  = threadIdx.x;
    const int wid  = tid >> 5;
    const int lane = tid & 31;
    const int g    = lane >> 2;       // group id
    const int t4   = lane & 3;
    const int mw   = wid & 3;         // M-split (4)
    const int nw   = wid >> 2;        // N-split (2)
    const int m0w  = mw * 32;

    // ldmatrix lane geometry
    const int lr = lane & 7, lm = lane >> 3;
    const int rowA = lr + (lm & 1) * 8, colA = (lm >> 1) * 8;   // A tiles (row-major [m][k])
    const int rowB = lr + (lm >> 1) * 8, colB = (lm & 1) * 8;   // B tiles (n-major [n][k])

    const uint32_t xs_u  = smem_u32(Xs);
    const uint32_t w1i_u = smem_u32(W1i);
    const uint32_t w1j_u = smem_u32(W1j);
    const uint32_t w2i_u = smem_u32(W2i);
    const uint32_t w2j_u = smem_u32(W2j);
    const uint32_t hi_u  = smem_u32(Hi);
    const uint32_t hj_u  = smem_u32(Hj);

    const int m0 = blockIdx.x * TM;

    // graph ids
    if (tid < TM) {
        int node = m0 + tid;
        int gg = -1;
        if (node < NNODE) {
            gg = graph_index[node];
            gg = gg < 0 ? 0 : (gg >= NGRAPH ? NGRAPH - 1 : gg);
        }
        gsh[tid] = gg;
    }

    // stage X: [node][k] fp16, k = h_T(0..127) || h_0(128..255)
    {
        int nl = tid >> 1, seg = tid & 1;
        int node = m0 + nl;
        __half2* dst = (__half2*)(Xs + nl * XP + seg * 128);
        if (node < NNODE) {
            const float4* src = (const float4*)((seg ? h_0 : h_T) + (size_t)node * NDIM);
            #pragma unroll 8
            for (int q = 0; q < 32; ++q) {
                float4 f = src[q];
                dst[q * 2]     = __floats2half2_rn(f.x, f.y);
                dst[q * 2 + 1] = __floats2half2_rn(f.z, f.w);
            }
        } else {
            #pragma unroll 8
            for (int q = 0; q < 64; ++q) dst[q] = __half2half2(__float2half(0.f));
        }
    }
    __syncthreads();

    float Oi[2][8][4];
    float Oj[2][8][4];
    #pragma unroll
    for (int i = 0; i < 2; ++i)
        #pragma unroll
        for (int j = 0; j < 8; ++j)
            #pragma unroll
            for (int r = 0; r < 4; ++r) { Oi[i][j][r] = 0.f; Oj[i][j][r] = 0.f; }

    const int n0w1 = nw * 32;   // L1 col base within 64-chunk
    const int n0w2 = nw * 64;   // L2 col base within 128

    #pragma unroll 1
    for (int c = 0; c < NCH; ++c) {
        // ---- stage W1i + W1j chunks ----
        stage_tile<64, 32, 264, W1P >(W1i, g_W1i + (size_t)c * 64 * 264, tid);
        stage_tile<64, 16, 136, W1JP>(W1j, g_W1j + (size_t)c * 64 * 136, tid);
        __syncthreads();

        // ---- L1i: D = X[128,256] @ W1i_chunk -> [128,64], warp tile 32x32 ----
        {
            float D[2][4][4];
            #pragma unroll
            for (int i = 0; i < 2; ++i)
                #pragma unroll
                for (int j = 0; j < 4; ++j)
                    #pragma unroll
                    for (int r = 0; r < 4; ++r) D[i][j][r] = 0.f;

            #pragma unroll 4
            for (int ks = 0; ks < 16; ++ks) {
                const int k0 = ks * 16;
                uint32_t a0[4], a1[4], b0[4], b1[4];
                ldm4(a0, xs_u  + ((m0w + rowA) * XP + k0 + colA) * 2);
                ldm4(a1, xs_u  + ((m0w + 16 + rowA) * XP + k0 + colA) * 2);
                ldm4(b0, w1i_u + ((n0w1 + rowB) * W1P + k0 + colB) * 2);
                ldm4(b1, w1i_u + ((n0w1 + 16 + rowB) * W1P + k0 + colB) * 2);
                mma16816(D[0][0], a0, b0[0], b0[1]);
                mma16816(D[0][1], a0, b0[2], b0[3]);
                mma16816(D[0][2], a0, b1[0], b1[1]);
                mma16816(D[0][3], a0, b1[2], b1[3]);
                mma16816(D[1][0], a1, b0[0], b0[1]);
                mma16816(D[1][1], a1, b0[2], b0[3]);
                mma16816(D[1][2], a1, b1[0], b1[1]);
                mma16816(D[1][3], a1, b1[2], b1[3]);
            }
            // bias + ReLU -> Hi (fp16)
            #pragma unroll
            for (int i = 0; i < 2; ++i)
                #pragma unroll
                for (int j = 0; j < 4; ++j) {
                    int col = n0w1 + j * 8 + t4 * 2;
                    float b0v = __ldg(&bi1[c * 64 + col]);
                    float b1v = __ldg(&bi1[c * 64 + col + 1]);
                    int r0 = m0w + i * 16 + g;
                    float v0 = fmaxf(D[i][j][0] + b0v, 0.f);
                    float v1 = fmaxf(D[i][j][1] + b1v, 0.f);
                    float v2 = fmaxf(D[i][j][2] + b0v, 0.f);
                    float v3 = fmaxf(D[i][j][3] + b1v, 0.f);
                    *(__half2*)(Hi + r0 * HP + col)       = __floats2half2_rn(v0, v1);
                    *(__half2*)(Hi + (r0 + 8) * HP + col) = __floats2half2_rn(v2, v3);
                }
        }
        // ---- L1j: K=128 ----
        {
            float D[2][4][4];
            #pragma unroll
            for (int i = 0; i < 2; ++i)
                #pragma unroll
                for (int j = 0; j < 4; ++j)
                    #pragma unroll
                    for (int r = 0; r < 4; ++r) D[i][j][r] = 0.f;

            #pragma unroll 4
            for (int ks = 0; ks < 8; ++ks) {
                const int k0 = ks * 16;
                uint32_t a0[4], a1[4], b0[4], b1[4];
                ldm4(a0, xs_u  + ((m0w + rowA) * XP + k0 + colA) * 2);
                ldm4(a1, xs_u  + ((m0w + 16 + rowA) * XP + k0 + colA) * 2);
                ldm4(b0, w1j_u + ((n0w1 + rowB) * W1JP + k0 + colB) * 2);
                ldm4(b1, w1j_u + ((n0w1 + 16 + rowB) * W1JP + k0 + colB) * 2);
                mma16816(D[0][0], a0, b0[0], b0[1]);
                mma16816(D[0][1], a0, b0[2], b0[3]);
                mma16816(D[0][2], a0, b1[0], b1[1]);
                mma16816(D[0][3], a0, b1[2], b1[3]);
                mma16816(D[1][0], a1, b0[0], b0[1]);
                mma16816(D[1][1], a1, b0[2], b0[3]);
                mma16816(D[1][2], a1, b1[0], b1[1]);
                mma16816(D[1][3], a1, b1[2], b1[3]);
            }
            #pragma unroll
            for (int i = 0; i < 2; ++i)
                #pragma unroll
                for (int j = 0; j < 4; ++j) {
                    int col = n0w1 + j * 8 + t4 * 2;
                    float b0v = __ldg(&bj1[c * 64 + col]);
                    float b1v = __ldg(&bj1[c * 64 + col + 1]);
                    int r0 = m0w + i * 16 + g;
                    float v0 = fmaxf(D[i][j][0] + b0v, 0.f);
                    float v1 = fmaxf(D[i][j][1] + b1v, 0.f);
                    float v2 = fmaxf(D[i][j][2] + b0v, 0.f);
                    float v3 = fmaxf(D[i][j][3] + b1v, 0.f);
                    *(__half2*)(Hj + r0 * HP + col)       = __floats2half2_rn(v0, v1);
                    *(__half2*)(Hj + (r0 + 8) * HP + col) = __floats2half2_rn(v2, v3);
                }
        }
        __syncthreads();   // W1 buffers free, H visible

        // ---- stage W2i + W2j chunks (k-slice c*64..+63) ----
        stage_tile<128, 8, 520, W2P>(W2i, g_W2i + c * 64, tid);
        stage_tile<128, 8, 520, W2P>(W2j, g_W2j + c * 64, tid);
        __syncthreads();

        // ---- L2: O += H[128,64] @ W2chunk[64,128], warp tile 32x64 ----
        #pragma unroll 2
        for (int ks = 0; ks < 4; ++ks) {
            const int k0 = ks * 16;
            uint32_t a0[4], a1[4], bt[4][4];
            ldm4(a0, hi_u + ((m0w + rowA) * HP + k0 + colA) * 2);
            ldm4(a1, hi_u + ((m0w + 16 + rowA) * HP + k0 + colA) * 2);
            #pragma unroll
            for (int tt = 0; tt < 4; ++tt)
                ldm4(bt[tt], w2i_u + ((n0w2 + tt * 16 + rowB) * W2P + k0 + colB) * 2);
            #pragma unroll
            for (int tt = 0; tt < 4; ++tt) {
                mma16816(Oi[0][tt * 2],     a0, bt[tt][0], bt[tt][1]);
                mma16816(Oi[0][tt * 2 + 1], a0, bt[tt][2], bt[tt][3]);
                mma16816(Oi[1][tt * 2],     a1, bt[tt][0], bt[tt][1]);
                mma16816(Oi[1][tt * 2 + 1], a1, bt[tt][2], bt[tt][3]);
            }
        }
        #pragma unroll 2
        for (int ks = 0; ks < 4; ++ks) {
            const int k0 = ks * 16;
            uint32_t a0[4], a1[4], bt[4][4];
            ldm4(a0, hj_u + ((m0w + rowA) * HP + k0 + colA) * 2);
            ldm4(a1, hj_u + ((m0w + 16 + rowA) * HP + k0 + colA) * 2);
            #pragma unroll
            for (int tt = 0; tt < 4; ++tt)
                ldm4(bt[tt], w2j_u + ((n0w2 + tt * 16 + rowB) * W2P + k0 + colB) * 2);
            #pragma unroll
            for (int tt = 0; tt < 4; ++tt) {
                mma16816(Oj[0][tt * 2],     a0, bt[tt][0], bt[tt][1]);
                mma16816(Oj[0][tt * 2 + 1], a0, bt[tt][2], bt[tt][3]);
                mma16816(Oj[1][tt * 2],     a1, bt[tt][0], bt[tt][1]);
                mma16816(Oj[1][tt * 2 + 1], a1, bt[tt][2], bt[tt][3]);
            }
        }
        __syncthreads();   // W2/H free for next chunk
    }

    // ---- final epilogue: Rv = sigmoid(Oi + bi2) * (Oj + bj2) -> RT (reuses X region) ----
    #pragma unroll
    for (int i = 0; i < 2; ++i)
        #pragma unroll
        for (int j = 0; j < 8; ++j) {
            int col = n0w2 + j * 8 + t4 * 2;
            float bi0 = __ldg(&bi2[col]), bi1v = __ldg(&bi2[col + 1]);
            float bj0 = __ldg(&bj2[col]), bj1v = __ldg(&bj2[col + 1]);
            int r0 = m0w + i * 16 + g;
            float g0 = 1.f / (1.f + __expf(-(Oi[i][j][0] + bi0)));
            float g1 = 1.f / (1.f + __expf(-(Oi[i][j][1] + bi1v)));
            float g2 = 1.f / (1.f + __expf(-(Oi[i][j][2] + bi0)));
            float g3 = 1.f / (1.f + __expf(-(Oi[i][j][3] + bi1v)));
            RT[r0 * RTP + col]           = g0 * (Oj[i][j][0] + bj0);
            RT[r0 * RTP + col + 1]       = g1 * (Oj[i][j][1] + bj1v);
            RT[(r0 + 8) * RTP + col]     = g2 * (Oj[i][j][2] + bj0);
            RT[(r0 + 8) * RTP + col + 1] = g3 * (Oj[i][j][3] + bj1v);
        }
    __syncthreads();

    // ---- segment-sum over sorted graph ids: 256 threads = 128 cols x 2 row-halves ----
    {
        const int c  = tid & 127;
        const int hf = tid >> 7;
        const int i0 = hf * 64, i1 = i0 + 64;
        float sum = 0.f;
        int gp = -1;
        #pragma unroll 4
        for (int i = i0; i < i1; ++i) {
            int gg = gsh[i];
            if (gg < 0) continue;
            if (gg != gp) {
                if (gp >= 0) atomicAdd(&R[gp * GDIM + c], sum);
                sum = 0.f;
                gp = gg;
            }
            sum += RT[i * RTP + c];
        }
        if (gp >= 0) atomicAdd(&R[gp * GDIM + c], sum);
    }
}

extern "C" void kernel_launch(void* const* d_in, const int* in_sizes, int n_in,
                              void* d_out, int out_size)
{
    (void)in_sizes; (void)n_in; (void)out_size;
    const float* h_T  = (const float*)d_in[0];
    const float* h_0  = (const float*)d_in[1];
    const int*   gidx = (const int*)d_in[2];
    const float* Wi1  = (const float*)d_in[3];
    const float* bi1  = (const float*)d_in[4];
    const float* Wi2  = (const float*)d_in[5];
    const float* bi2  = (const float*)d_in[6];
    const float* Wj1  = (const float*)d_in[7];
    const float* bj1  = (const float*)d_in[8];
    const float* Wj2  = (const float*)d_in[9];
    const float* bj2  = (const float*)d_in[10];
    float* R = (float*)d_out;

    cudaFuncSetAttribute(readout_mma_kernel,
                         cudaFuncAttributeMaxDynamicSharedMemorySize, SMEM_BYTES);

    prep_w1_kernel<<<(HIDDEN * (256 + 128) + 255) / 256, 256>>>(Wi1, Wj1);
    prep_w2_kernel<<<(2 * HIDDEN * GDIM + 255) / 256, 256>>>(Wi2, Wj2);
    zero_out_kernel<<<(NGRAPH * GDIM + 255) / 256, 256>>>(R, NGRAPH * GDIM);
    readout_mma_kernel<<<NTILES, THREADS, SMEM_BYTES>>>(
        h_T, h_0, gidx, bi1, bi2, bj1, bj2, R);
}

// round 8
// speedup vs baseline: 7.2203x; 1.0511x over previous
#include <cuda_runtime.h>
#include <cuda_fp16.h>
#include <cstdint>

#define NNODE   200000
#define NDIM    128
#define HIDDEN  512
#define GDIM    128
#define NGRAPH  1024

#define TM      64
#define THREADS 256
#define NTILES  (NNODE / TM)               // 3125, exact
#define NCH     8                           // hidden chunks of 64

// smem pitches (half elements); row strides ≡ 4 words mod 32 -> conflict-free ldmatrix
#define XP   264     // X  [64][264]
#define W1P  264     // W1i chunk [64][264] (K=256)
#define W1JP 136     // W1j chunk [64][136] (K=128)
#define W2P  72      // W2 chunk [128][72]  (K=64)
#define HP   72      // H  [64][72]
#define RTP  132     // RT [64][132] f32

// smem byte offsets
#define SX    0                        // 64*264*2 = 33792 (reused as RT: 64*132*4 = 33792)
#define SW    33792                    // W1i 33792 ; W2i/W2j reuse this region
#define SW1J  (SW + 33792)             // W1j 17408 (region ends 84992)
#define SW2I  SW
#define SW2J  (SW + 18432)
#define SH    84992                    // Hi 9216
#define SHJ   (SH + 9216)              // Hj 9216
#define SG    103424                   // gsh 64 ints
#define SMEM_BYTES 103680              // 2 CTAs/SM: 207360 < 227KB carveout

// prepped fp16 weights, n-major [n][k] with padded pitch
__device__ __align__(16) __half g_W1i[HIDDEN * 264];   // [512][264], k<256 valid
__device__ __align__(16) __half g_W1j[HIDDEN * 136];   // [512][136], k<128 valid
__device__ __align__(16) __half g_W2i[GDIM * 520];     // [128][520], k<512 valid
__device__ __align__(16) __half g_W2j[GDIM * 520];

// ---------------- PTX helpers ----------------
__device__ __forceinline__ uint32_t smem_u32(const void* p) {
    uint32_t a;
    asm("{ .reg .u64 t; cvta.to.shared.u64 t, %1; cvt.u32.u64 %0, t; }" : "=r"(a) : "l"(p));
    return a;
}
__device__ __forceinline__ void ldm4(uint32_t* r, uint32_t addr) {
    asm volatile("ldmatrix.sync.aligned.m8n8.x4.shared.b16 {%0,%1,%2,%3}, [%4];"
                 : "=r"(r[0]), "=r"(r[1]), "=r"(r[2]), "=r"(r[3]) : "r"(addr));
}
__device__ __forceinline__ void mma16816(float* d, const uint32_t* a, uint32_t b0, uint32_t b1) {
    asm volatile("mma.sync.aligned.m16n8k16.row.col.f32.f16.f16.f32 "
                 "{%0,%1,%2,%3}, {%4,%5,%6,%7}, {%8,%9}, {%0,%1,%2,%3};"
                 : "+f"(d[0]), "+f"(d[1]), "+f"(d[2]), "+f"(d[3])
                 : "r"(a[0]), "r"(a[1]), "r"(a[2]), "r"(a[3]), "r"(b0), "r"(b1));
}
__device__ __forceinline__ void cp_async16(uint32_t dst, const void* src) {
    asm volatile("cp.async.cg.shared.global [%0], [%1], 16;" :: "r"(dst), "l"(src));
}
__device__ __forceinline__ void cp_commit_wait0() {
    asm volatile("cp.async.commit_group;");
    asm volatile("cp.async.wait_group 0;" ::: "memory");
}

// ---------------- prep kernels ----------------
__global__ void prep_w1_kernel(const float* __restrict__ Wi1, const float* __restrict__ Wj1)
{
    int idx = blockIdx.x * blockDim.x + threadIdx.x;
    const int NI = HIDDEN * 256;           // Wi1: [256 k][512 n]
    const int NJ = HIDDEN * 128;           // Wj1: [128 k][512 n]
    if (idx < NI) {
        int n = idx >> 8, k = idx & 255;
        g_W1i[n * 264 + k] = __float2half_rn(Wi1[k * HIDDEN + n]);
    } else if (idx < NI + NJ) {
        int t = idx - NI;
        int n = t >> 7, k = t & 127;
        g_W1j[n * 136 + k] = __float2half_rn(Wj1[k * HIDDEN + n]);
    }
}
__global__ void prep_w2_kernel(const float* __restrict__ Wi2, const float* __restrict__ Wj2)
{
    int idx = blockIdx.x * blockDim.x + threadIdx.x;   // over 2 * 512 * 128
    const int NT = HIDDEN * GDIM;
    if (idx >= 2 * NT) return;
    int net = idx >= NT;
    int t = net ? idx - NT : idx;
    int k = t >> 7, n = t & 127;           // W2: [512 k][128 n]
    __half v = __float2half_rn((net ? Wj2 : Wi2)[k * GDIM + n]);
    if (net) g_W2j[n * 520 + k] = v;
    else     g_W2i[n * 520 + k] = v;
}

__global__ void zero_out_kernel(float* __restrict__ R, int n)
{
    int i = blockIdx.x * blockDim.x + threadIdx.x;
    if (i < n) R[i] = 0.f;
}

// async stage: RWS rows x CQ uint4 per row, src pitch SP halves, dst pitch DP halves
template <int RWS, int CQ, int SP, int DP>
__device__ __forceinline__ void stage_async(uint32_t dst_u, const __half* __restrict__ src, int tid)
{
    const int nq = RWS * CQ;
    #pragma unroll
    for (int f = tid; f < nq; f += THREADS) {
        int row = f / CQ, q = f - row * CQ;
        cp_async16(dst_u + (uint32_t)(row * DP + q * 8) * 2, src + row * SP + q * 8);
    }
}

// ---------------- main kernel ----------------
__global__ __launch_bounds__(THREADS, 2)
void readout_mma_kernel(
    const float* __restrict__ h_T, const float* __restrict__ h_0,
    const int* __restrict__ graph_index,
    const float* __restrict__ bi1, const float* __restrict__ bi2,
    const float* __restrict__ bj1, const float* __restrict__ bj2,
    float* __restrict__ R)
{
    extern __shared__ __align__(16) char sm[];
    __half* Xs  = (__half*)(sm + SX);
    int*    gsh = (int*)(sm + SG);
    float*  RT  = (float*)(sm + SX);

    const int tid  = threadIdx.x;
    const int wid  = tid >> 5;
    const int lane = tid & 31;
    const int g    = lane >> 2;       // group id (quad row)
    const int t4   = lane & 3;
    const int mw   = wid & 1;         // M-split (2)
    const int nw   = wid >> 1;        // N-split (4)
    const int m0w  = mw * 32;

    // ldmatrix lane geometry
    const int lr = lane & 7, lm = lane >> 3;
    const int rowA = lr + (lm & 1) * 8, colA = (lm >> 1) * 8;   // A tiles (row-major [m][k])
    const int rowB = lr + (lm >> 1) * 8, colB = (lm & 1) * 8;   // B tiles (n-major [n][k])

    const uint32_t xs_u  = smem_u32(sm + SX);
    const uint32_t w1i_u = smem_u32(sm + SW);
    const uint32_t w1j_u = smem_u32(sm + SW1J);
    const uint32_t w2i_u = smem_u32(sm + SW2I);
    const uint32_t w2j_u = smem_u32(sm + SW2J);
    const uint32_t hi_u  = smem_u32(sm + SH);
    const uint32_t hj_u  = smem_u32(sm + SHJ);
    __half* Hi = (__half*)(sm + SH);
    __half* Hj = (__half*)(sm + SHJ);

    const int m0 = blockIdx.x * TM;

    // graph ids (grid exactly covers NNODE)
    if (tid < TM) {
        int gg = graph_index[m0 + tid];
        gsh[tid] = gg < 0 ? 0 : (gg >= NGRAPH ? NGRAPH - 1 : gg);
    }

    // stage X: [node][k] fp16, k = h_T(0..127) || h_0(128..255); 4 threads/row
    {
        int nl = tid >> 2, seg = tid & 3;
        const float* base = (seg < 2) ? h_T : h_0;
        const float4* src = (const float4*)(base + (size_t)(m0 + nl) * NDIM + (seg & 1) * 64);
        __half2* dst = (__half2*)(Xs + nl * XP + seg * 64);
        #pragma unroll 8
        for (int q = 0; q < 16; ++q) {
            float4 f = src[q];
            dst[q * 2]     = __floats2half2_rn(f.x, f.y);
            dst[q * 2 + 1] = __floats2half2_rn(f.z, f.w);
        }
    }
    __syncthreads();

    float Oi[2][4][4];
    float Oj[2][4][4];
    #pragma unroll
    for (int i = 0; i < 2; ++i)
        #pragma unroll
        for (int j = 0; j < 4; ++j)
            #pragma unroll
            for (int r = 0; r < 4; ++r) { Oi[i][j][r] = 0.f; Oj[i][j][r] = 0.f; }

    const int n0w1 = nw * 16;   // L1 col base within 64-chunk (warp tile 32x16)
    const int n0w2 = nw * 32;   // L2 col base within 128 (warp tile 32x32)

    #pragma unroll 1
    for (int c = 0; c < NCH; ++c) {
        // ---- stage W1i + W1j chunks (async) ----
        stage_async<64, 32, 264, W1P >(w1i_u, g_W1i + (size_t)c * 64 * 264, tid);
        stage_async<64, 16, 136, W1JP>(w1j_u, g_W1j + (size_t)c * 64 * 136, tid);
        cp_commit_wait0();
        __syncthreads();

        // ---- L1i: X[64,256] @ W1i_chunk -> [64,64], warp tile 32x16 ----
        {
            float D[2][2][4];
            #pragma unroll
            for (int i = 0; i < 2; ++i)
                #pragma unroll
                for (int j = 0; j < 2; ++j)
                    #pragma unroll
                    for (int r = 0; r < 4; ++r) D[i][j][r] = 0.f;

            #pragma unroll 4
            for (int ks = 0; ks < 16; ++ks) {
                const int k0 = ks * 16;
                uint32_t a0[4], a1[4], b0[4];
                ldm4(a0, xs_u  + ((m0w + rowA) * XP + k0 + colA) * 2);
                ldm4(a1, xs_u  + ((m0w + 16 + rowA) * XP + k0 + colA) * 2);
                ldm4(b0, w1i_u + ((n0w1 + rowB) * W1P + k0 + colB) * 2);
                mma16816(D[0][0], a0, b0[0], b0[1]);
                mma16816(D[0][1], a0, b0[2], b0[3]);
                mma16816(D[1][0], a1, b0[0], b0[1]);
                mma16816(D[1][1], a1, b0[2], b0[3]);
            }
            #pragma unroll
            for (int i = 0; i < 2; ++i)
                #pragma unroll
                for (int j = 0; j < 2; ++j) {
                    int col = n0w1 + j * 8 + t4 * 2;
                    float b0v = __ldg(&bi1[c * 64 + col]);
                    float b1v = __ldg(&bi1[c * 64 + col + 1]);
                    int r0 = m0w + i * 16 + g;
                    float v0 = fmaxf(D[i][j][0] + b0v, 0.f);
                    float v1 = fmaxf(D[i][j][1] + b1v, 0.f);
                    float v2 = fmaxf(D[i][j][2] + b0v, 0.f);
                    float v3 = fmaxf(D[i][j][3] + b1v, 0.f);
                    *(__half2*)(Hi + r0 * HP + col)       = __floats2half2_rn(v0, v1);
                    *(__half2*)(Hi + (r0 + 8) * HP + col) = __floats2half2_rn(v2, v3);
                }
        }
        // ---- L1j: K=128 ----
        {
            float D[2][2][4];
            #pragma unroll
            for (int i = 0; i < 2; ++i)
                #pragma unroll
                for (int j = 0; j < 2; ++j)
                    #pragma unroll
                    for (int r = 0; r < 4; ++r) D[i][j][r] = 0.f;

            #pragma unroll 4
            for (int ks = 0; ks < 8; ++ks) {
                const int k0 = ks * 16;
                uint32_t a0[4], a1[4], b0[4];
                ldm4(a0, xs_u  + ((m0w + rowA) * XP + k0 + colA) * 2);
                ldm4(a1, xs_u  + ((m0w + 16 + rowA) * XP + k0 + colA) * 2);
                ldm4(b0, w1j_u + ((n0w1 + rowB) * W1JP + k0 + colB) * 2);
                mma16816(D[0][0], a0, b0[0], b0[1]);
                mma16816(D[0][1], a0, b0[2], b0[3]);
                mma16816(D[1][0], a1, b0[0], b0[1]);
                mma16816(D[1][1], a1, b0[2], b0[3]);
            }
            #pragma unroll
            for (int i = 0; i < 2; ++i)
                #pragma unroll
                for (int j = 0; j < 2; ++j) {
                    int col = n0w1 + j * 8 + t4 * 2;
                    float b0v = __ldg(&bj1[c * 64 + col]);
                    float b1v = __ldg(&bj1[c * 64 + col + 1]);
                    int r0 = m0w + i * 16 + g;
                    float v0 = fmaxf(D[i][j][0] + b0v, 0.f);
                    float v1 = fmaxf(D[i][j][1] + b1v, 0.f);
                    float v2 = fmaxf(D[i][j][2] + b0v, 0.f);
                    float v3 = fmaxf(D[i][j][3] + b1v, 0.f);
                    *(__half2*)(Hj + r0 * HP + col)       = __floats2half2_rn(v0, v1);
                    *(__half2*)(Hj + (r0 + 8) * HP + col) = __floats2half2_rn(v2, v3);
                }
        }
        __syncthreads();   // W1 consumed, H visible

        // ---- stage W2i + W2j chunks (k-slice c*64..+63, async) ----
        stage_async<128, 8, 520, W2P>(w2i_u, g_W2i + c * 64, tid);
        stage_async<128, 8, 520, W2P>(w2j_u, g_W2j + c * 64, tid);
        cp_commit_wait0();
        __syncthreads();

        // ---- L2: O += H[64,64] @ W2chunk[64,128], warp tile 32x32 ----
        #pragma unroll 2
        for (int ks = 0; ks < 4; ++ks) {
            const int k0 = ks * 16;
            uint32_t a0[4], a1[4], bt[2][4];
            ldm4(a0, hi_u + ((m0w + rowA) * HP + k0 + colA) * 2);
            ldm4(a1, hi_u + ((m0w + 16 + rowA) * HP + k0 + colA) * 2);
            #pragma unroll
            for (int tt = 0; tt < 2; ++tt)
                ldm4(bt[tt], w2i_u + ((n0w2 + tt * 16 + rowB) * W2P + k0 + colB) * 2);
            #pragma unroll
            for (int tt = 0; tt < 2; ++tt) {
                mma16816(Oi[0][tt * 2],     a0, bt[tt][0], bt[tt][1]);
                mma16816(Oi[0][tt * 2 + 1], a0, bt[tt][2], bt[tt][3]);
                mma16816(Oi[1][tt * 2],     a1, bt[tt][0], bt[tt][1]);
                mma16816(Oi[1][tt * 2 + 1], a1, bt[tt][2], bt[tt][3]);
            }
        }
        #pragma unroll 2
        for (int ks = 0; ks < 4; ++ks) {
            const int k0 = ks * 16;
            uint32_t a0[4], a1[4], bt[2][4];
            ldm4(a0, hj_u + ((m0w + rowA) * HP + k0 + colA) * 2);
            ldm4(a1, hj_u + ((m0w + 16 + rowA) * HP + k0 + colA) * 2);
            #pragma unroll
            for (int tt = 0; tt < 2; ++tt)
                ldm4(bt[tt], w2j_u + ((n0w2 + tt * 16 + rowB) * W2P + k0 + colB) * 2);
            #pragma unroll
            for (int tt = 0; tt < 2; ++tt) {
                mma16816(Oj[0][tt * 2],     a0, bt[tt][0], bt[tt][1]);
                mma16816(Oj[0][tt * 2 + 1], a0, bt[tt][2], bt[tt][3]);
                mma16816(Oj[1][tt * 2],     a1, bt[tt][0], bt[tt][1]);
                mma16816(Oj[1][tt * 2 + 1], a1, bt[tt][2], bt[tt][3]);
            }
        }
        __syncthreads();   // W2/H free for next chunk
    }

    // ---- final epilogue: Rv = sigmoid(Oi + bi2) * (Oj + bj2) -> RT (reuses X region) ----
    #pragma unroll
    for (int i = 0; i < 2; ++i)
        #pragma unroll
        for (int j = 0; j < 4; ++j) {
            int col = n0w2 + j * 8 + t4 * 2;
            float bi0 = __ldg(&bi2[col]), bi1v = __ldg(&bi2[col + 1]);
            float bj0 = __ldg(&bj2[col]), bj1v = __ldg(&bj2[col + 1]);
            int r0 = m0w + i * 16 + g;
            float g0 = 1.f / (1.f + __expf(-(Oi[i][j][0] + bi0)));
            float g1 = 1.f / (1.f + __expf(-(Oi[i][j][1] + bi1v)));
            float g2 = 1.f / (1.f + __expf(-(Oi[i][j][2] + bi0)));
            float g3 = 1.f / (1.f + __expf(-(Oi[i][j][3] + bi1v)));
            RT[r0 * RTP + col]           = g0 * (Oj[i][j][0] + bj0);
            RT[r0 * RTP + col + 1]       = g1 * (Oj[i][j][1] + bj1v);
            RT[(r0 + 8) * RTP + col]     = g2 * (Oj[i][j][2] + bj0);
            RT[(r0 + 8) * RTP + col + 1] = g3 * (Oj[i][j][3] + bj1v);
        }
    __syncthreads();

    // ---- segment-sum over sorted graph ids: 256 threads = 128 cols x 2 row-halves ----
    {
        const int c  = tid & 127;
        const int hf = tid >> 7;
        const int i0 = hf * 32, i1 = i0 + 32;
        float sum = 0.f;
        int gp = -1;
        #pragma unroll 4
        for (int i = i0; i < i1; ++i) {
            int gg = gsh[i];
            if (gg != gp) {
                if (gp >= 0) atomicAdd(&R[gp * GDIM + c], sum);
                sum = 0.f;
                gp = gg;
            }
            sum += RT[i * RTP + c];
        }
        if (gp >= 0) atomicAdd(&R[gp * GDIM + c], sum);
    }
}

extern "C" void kernel_launch(void* const* d_in, const int* in_sizes, int n_in,
                              void* d_out, int out_size)
{
    (void)in_sizes; (void)n_in; (void)out_size;
    const float* h_T  = (const float*)d_in[0];
    const float* h_0  = (const float*)d_in[1];
    const int*   gidx = (const int*)d_in[2];
    const float* Wi1  = (const float*)d_in[3];
    const float* bi1  = (const float*)d_in[4];
    const float* Wi2  = (const float*)d_in[5];
    const float* bi2  = (const float*)d_in[6];
    const float* Wj1  = (const float*)d_in[7];
    const float* bj1  = (const float*)d_in[8];
    const float* Wj2  = (const float*)d_in[9];
    const float* bj2  = (const float*)d_in[10];
    float* R = (float*)d_out;

    cudaFuncSetAttribute(readout_mma_kernel,
                         cudaFuncAttributeMaxDynamicSharedMemorySize, SMEM_BYTES);

    prep_w1_kernel<<<(HIDDEN * (256 + 128) + 255) / 256, 256>>>(Wi1, Wj1);
    prep_w2_kernel<<<(2 * HIDDEN * GDIM + 255) / 256, 256>>>(Wi2, Wj2);
    zero_out_kernel<<<(NGRAPH * GDIM + 255) / 256, 256>>>(R, NGRAPH * GDIM);
    readout_mma_kernel<<<NTILES, THREADS, SMEM_BYTES>>>(
        h_T, h_0, gidx, bi1, bi2, bj1, bj2, R);
}

// round 10
// speedup vs baseline: 8.6957x; 1.2043x over previous
#include <cuda_runtime.h>
#include <cuda_fp16.h>
#include <cstdint>

#define NNODE   200000
#define NDIM    128
#define HIDDEN  512
#define GDIM    128
#define NGRAPH  1024

#define TM      64
#define THREADS 256
#define NTILES  (NNODE / TM)               // 3125, exact
#define NCH     8                           // hidden chunks of 64
#define XC      6                           // X A-frag k-steps cached in regs (k < 96)

// smem pitches (half elements); row strides ≡ 4 words mod 32 -> conflict-free ldmatrix
#define XP   264     // X  [64][264]
#define W2P  72      // W2 chunk [128][72]  (K=64)
#define HP   72      // H  [64][72]
#define JVP  136     // jv [64][136] fp16
#define RTP  132     // RT [64][132] f32

// smem byte offsets
#define SX    0                        // 64*264*2 = 33792 (reused as RT: 64*132*4 = 33792)
#define SW1   33792                    // W1 chunk: max(W1i 64*264*2=33792, W1j 64*136*2=17408)
#define SW2   67584                    // 128*72*2 = 18432
#define SH    86016                    // 64*72*2  = 9216
#define SJV   95232                    // 64*136*2 = 17408
#define SG    112640                   // gsh 64 ints
#define SMEM_BYTES 112896              // x2 CTA = 225792 <= ~227KB/SM carveout

// prepped fp16 weights, n-major [n][k] with padded pitch
__device__ __align__(16) __half g_W1i[HIDDEN * 264];   // [512][264], k<256 valid
__device__ __align__(16) __half g_W1j[HIDDEN * 136];   // [512][136], k<128 valid
__device__ __align__(16) __half g_W2i[GDIM * 520];     // [128][520], k<512 valid
__device__ __align__(16) __half g_W2j[GDIM * 520];

// ---------------- PTX helpers ----------------
__device__ __forceinline__ uint32_t smem_u32(const void* p) {
    uint32_t a;
    asm("{ .reg .u64 t; cvta.to.shared.u64 t, %1; cvt.u32.u64 %0, t; }" : "=r"(a) : "l"(p));
    return a;
}
__device__ __forceinline__ void ldm4(uint32_t* r, uint32_t addr) {
    asm volatile("ldmatrix.sync.aligned.m8n8.x4.shared.b16 {%0,%1,%2,%3}, [%4];"
                 : "=r"(r[0]), "=r"(r[1]), "=r"(r[2]), "=r"(r[3]) : "r"(addr));
}
__device__ __forceinline__ void mma16816(float* d, const uint32_t* a, uint32_t b0, uint32_t b1) {
    asm volatile("mma.sync.aligned.m16n8k16.row.col.f32.f16.f16.f32 "
                 "{%0,%1,%2,%3}, {%4,%5,%6,%7}, {%8,%9}, {%0,%1,%2,%3};"
                 : "+f"(d[0]), "+f"(d[1]), "+f"(d[2]), "+f"(d[3])
                 : "r"(a[0]), "r"(a[1]), "r"(a[2]), "r"(a[3]), "r"(b0), "r"(b1));
}
__device__ __forceinline__ void cp_async16(uint32_t dst, const void* src) {
    asm volatile("cp.async.cg.shared.global [%0], [%1], 16;" :: "r"(dst), "l"(src));
}
__device__ __forceinline__ void cp_commit() {
    asm volatile("cp.async.commit_group;");
}
template <int N>
__device__ __forceinline__ void cp_wait() {
    asm volatile("cp.async.wait_group %0;" :: "n"(N) : "memory");
}

// ---------------- prep kernels ----------------
__global__ void prep_w1_kernel(const float* __restrict__ Wi1, const float* __restrict__ Wj1)
{
    int idx = blockIdx.x * blockDim.x + threadIdx.x;
    const int NI = HIDDEN * 256;           // Wi1: [256 k][512 n]
    const int NJ = HIDDEN * 128;           // Wj1: [128 k][512 n]
    if (idx < NI) {
        int n = idx >> 8, k = idx & 255;
        g_W1i[n * 264 + k] = __float2half_rn(Wi1[k * HIDDEN + n]);
    } else if (idx < NI + NJ) {
        int t = idx - NI;
        int n = t >> 7, k = t & 127;
        g_W1j[n * 136 + k] = __float2half_rn(Wj1[k * HIDDEN + n]);
    }
}
__global__ void prep_w2_kernel(const float* __restrict__ Wi2, const float* __restrict__ Wj2)
{
    int idx = blockIdx.x * blockDim.x + threadIdx.x;   // over 2 * 512 * 128
    const int NT = HIDDEN * GDIM;
    if (idx >= 2 * NT) return;
    int net = idx >= NT;
    int t = net ? idx - NT : idx;
    int k = t >> 7, n = t & 127;           // W2: [512 k][128 n]
    __half v = __float2half_rn((net ? Wj2 : Wi2)[k * GDIM + n]);
    if (net) g_W2j[n * 520 + k] = v;
    else     g_W2i[n * 520 + k] = v;
}

__global__ void zero_out_kernel(float* __restrict__ R, int n)
{
    int i = blockIdx.x * blockDim.x + threadIdx.x;
    if (i < n) R[i] = 0.f;
}

// async stage: RWS rows x CQ uint4 per row, src pitch SP halves, dst pitch DP halves
template <int RWS, int CQ, int SP, int DP>
__device__ __forceinline__ void stage_async(uint32_t dst_u, const __half* __restrict__ src, int tid)
{
    const int nq = RWS * CQ;
    #pragma unroll
    for (int f = tid; f < nq; f += THREADS) {
        int row = f / CQ, q = f - row * CQ;
        cp_async16(dst_u + (uint32_t)(row * DP + q * 8) * 2, src + row * SP + q * 8);
    }
}

// ---------------- one net phase: O += full 2-layer MLP for one net ----------------
// KD = input K (128 for j, 256 for i). W1 image pitch = KD + 8.
template <int KD>
__device__ __forceinline__ void run_phase(
    const __half* __restrict__ gW1, const __half* __restrict__ gW2,
    const float* __restrict__ b1,
    uint32_t xs_u, uint32_t w1_u, uint32_t w2_u, uint32_t h_u, __half* Hs,
    const uint32_t (&xa0)[XC][4], const uint32_t (&xa1)[XC][4],
    float (&O)[2][4][4],
    int tid, int m0w, int n0w1, int n0w2, int g, int t4,
    int rowA, int colA, int rowB, int colB)
{
    constexpr int W1SP = KD + 8;
    constexpr int NKS  = KD / 16;

    #pragma unroll 1
    for (int c = 0; c < NCH; ++c) {
        // ---- stage W1 chunk (group 0); overlaps previous chunk's L2 ----
        stage_async<64, KD / 8, W1SP, W1SP>(w1_u, gW1 + (size_t)c * 64 * W1SP, tid);
        cp_commit();
        __syncthreads();                 // prev L2 done: W2 + H regions free
        // ---- stage W2 k-slice (group 1); lands during L1 compute ----
        stage_async<128, 8, 520, W2P>(w2_u, gW2 + c * 64, tid);
        cp_commit();
        cp_wait<1>();                    // W1 arrived
        __syncthreads();

        // ---- L1: X[64,KD] @ W1chunk -> H[64,64]; warp tile 32x16 ----
        {
            float D[2][2][4];
            #pragma unroll
            for (int i = 0; i < 2; ++i)
                #pragma unroll
                for (int j = 0; j < 2; ++j)
                    #pragma unroll
                    for (int r = 0; r < 4; ++r) D[i][j][r] = 0.f;

            #pragma unroll
            for (int ks = 0; ks < NKS; ++ks) {
                const int k0 = ks * 16;
                uint32_t t0[4], t1[4];
                if (ks >= XC) {
                    ldm4(t0, xs_u + ((m0w + rowA) * XP + k0 + colA) * 2);
                    ldm4(t1, xs_u + ((m0w + 16 + rowA) * XP + k0 + colA) * 2);
                }
                const uint32_t* a0 = (ks < XC) ? xa0[ks] : t0;
                const uint32_t* a1 = (ks < XC) ? xa1[ks] : t1;
                uint32_t b0[4];
                ldm4(b0, w1_u + ((n0w1 + rowB) * W1SP + k0 + colB) * 2);
                mma16816(D[0][0], a0, b0[0], b0[1]);
                mma16816(D[0][1], a0, b0[2], b0[3]);
                mma16816(D[1][0], a1, b0[0], b0[1]);
                mma16816(D[1][1], a1, b0[2], b0[3]);
            }
            // bias + ReLU -> H (fp16)
            #pragma unroll
            for (int i = 0; i < 2; ++i)
                #pragma unroll
                for (int j = 0; j < 2; ++j) {
                    int col = n0w1 + j * 8 + t4 * 2;
                    float b0v = __ldg(&b1[c * 64 + col]);
                    float b1v = __ldg(&b1[c * 64 + col + 1]);
                    int r0 = m0w + i * 16 + g;
                    float v0 = fmaxf(D[i][j][0] + b0v, 0.f);
                    float v1 = fmaxf(D[i][j][1] + b1v, 0.f);
                    float v2 = fmaxf(D[i][j][2] + b0v, 0.f);
                    float v3 = fmaxf(D[i][j][3] + b1v, 0.f);
                    *(__half2*)(Hs + r0 * HP + col)       = __floats2half2_rn(v0, v1);
                    *(__half2*)(Hs + (r0 + 8) * HP + col) = __floats2half2_rn(v2, v3);
                }
        }
        cp_wait<0>();                    // W2 arrived
        __syncthreads();                 // H + W2 visible

        // ---- L2: O += H[64,64] @ W2chunk[64,128]; warp tile 32x32 ----
        #pragma unroll 2
        for (int ks = 0; ks < 4; ++ks) {
            const int k0 = ks * 16;
            uint32_t a0[4], a1[4], bt[2][4];
            ldm4(a0, h_u + ((m0w + rowA) * HP + k0 + colA) * 2);
            ldm4(a1, h_u + ((m0w + 16 + rowA) * HP + k0 + colA) * 2);
            #pragma unroll
            for (int tt = 0; tt < 2; ++tt)
                ldm4(bt[tt], w2_u + ((n0w2 + tt * 16 + rowB) * W2P + k0 + colB) * 2);
            #pragma unroll
            for (int tt = 0; tt < 2; ++tt) {
                mma16816(O[0][tt * 2],     a0, bt[tt][0], bt[tt][1]);
                mma16816(O[0][tt * 2 + 1], a0, bt[tt][2], bt[tt][3]);
                mma16816(O[1][tt * 2],     a1, bt[tt][0], bt[tt][1]);
                mma16816(O[1][tt * 2 + 1], a1, bt[tt][2], bt[tt][3]);
            }
        }
    }
}

// ---------------- main kernel ----------------
__global__ __launch_bounds__(THREADS, 2)
void readout_mma_kernel(
    const float* __restrict__ h_T, const float* __restrict__ h_0,
    const int* __restrict__ graph_index,
    const float* __restrict__ bi1, const float* __restrict__ bi2,
    const float* __restrict__ bj1, const float* __restrict__ bj2,
    float* __restrict__ R)
{
    extern __shared__ __align__(16) char sm[];
    __half* Xs  = (__half*)(sm + SX);
    __half* Hs  = (__half*)(sm + SH);
    __half* jv  = (__half*)(sm + SJV);
    int*    gsh = (int*)(sm + SG);
    float*  RT  = (float*)(sm + SX);

    const int tid  = threadIdx.x;
    const int wid  = tid >> 5;
    const int lane = tid & 31;
    const int g    = lane >> 2;
    const int t4   = lane & 3;
    const int mw   = wid & 1;         // M-split (2)
    const int nw   = wid >> 1;        // N-split (4)
    const int m0w  = mw * 32;

    const int lr = lane & 7, lm = lane >> 3;
    const int rowA = lr + (lm & 1) * 8, colA = (lm >> 1) * 8;   // A (row-major [m][k])
    const int rowB = lr + (lm >> 1) * 8, colB = (lm & 1) * 8;   // B (n-major [n][k])

    const uint32_t xs_u = smem_u32(sm + SX);
    const uint32_t w1_u = smem_u32(sm + SW1);
    const uint32_t w2_u = smem_u32(sm + SW2);
    const uint32_t h_u  = smem_u32(sm + SH);

    const int m0 = blockIdx.x * TM;

    if (tid < TM) {
        int gg = graph_index[m0 + tid];
        gsh[tid] = gg < 0 ? 0 : (gg >= NGRAPH ? NGRAPH - 1 : gg);
    }

    // stage X: [node][k] fp16, k = h_T(0..127) || h_0(128..255); 4 threads/row
    {
        int nl = tid >> 2, seg = tid & 3;
        const float* base = (seg < 2) ? h_T : h_0;
        const float4* src = (const float4*)(base + (size_t)(m0 + nl) * NDIM + (seg & 1) * 64);
        __half2* dst = (__half2*)(Xs + nl * XP + seg * 64);
        #pragma unroll 8
        for (int q = 0; q < 16; ++q) {
            float4 f = src[q];
            dst[q * 2]     = __floats2half2_rn(f.x, f.y);
            dst[q * 2 + 1] = __floats2half2_rn(f.z, f.w);
        }
    }
    __syncthreads();

    // ---- cache X A-fragments for k < 16*XC (invariant across chunks/phases) ----
    uint32_t xa0[XC][4], xa1[XC][4];
    #pragma unroll
    for (int ks = 0; ks < XC; ++ks) {
        ldm4(xa0[ks], xs_u + ((m0w + rowA) * XP + ks * 16 + colA) * 2);
        ldm4(xa1[ks], xs_u + ((m0w + 16 + rowA) * XP + ks * 16 + colA) * 2);
    }

    const int n0w1 = nw * 16;
    const int n0w2 = nw * 32;

    float O[2][4][4];

    // ================= phase 1: j-net (K = 128) =================
    #pragma unroll
    for (int i = 0; i < 2; ++i)
        #pragma unroll
        for (int j = 0; j < 4; ++j)
            #pragma unroll
            for (int r = 0; r < 4; ++r) O[i][j][r] = 0.f;

    run_phase<NDIM>(g_W1j, g_W2j, bj1, xs_u, w1_u, w2_u, h_u, Hs,
                    xa0, xa1, O, tid, m0w, n0w1, n0w2, g, t4,
                    rowA, colA, rowB, colB);

    // j epilogue: jv = O + bj2 (fp16)
    #pragma unroll
    for (int i = 0; i < 2; ++i)
        #pragma unroll
        for (int j = 0; j < 4; ++j) {
            int col = n0w2 + j * 8 + t4 * 2;
            float bj0 = __ldg(&bj2[col]), bj1v = __ldg(&bj2[col + 1]);
            int r0 = m0w + i * 16 + g;
            *(__half2*)(jv + r0 * JVP + col) =
                __floats2half2_rn(O[i][j][0] + bj0, O[i][j][1] + bj1v);
            *(__half2*)(jv + (r0 + 8) * JVP + col) =
                __floats2half2_rn(O[i][j][2] + bj0, O[i][j][3] + bj1v);
        }

    // ================= phase 2: i-net (K = 256) =================
    #pragma unroll
    for (int i = 0; i < 2; ++i)
        #pragma unroll
        for (int j = 0; j < 4; ++j)
            #pragma unroll
            for (int r = 0; r < 4; ++r) O[i][j][r] = 0.f;

    run_phase<2 * NDIM>(g_W1i, g_W2i, bi1, xs_u, w1_u, w2_u, h_u, Hs,
                        xa0, xa1, O, tid, m0w, n0w1, n0w2, g, t4,
                        rowA, colA, rowB, colB);

    // i epilogue: RT = sigmoid(O + bi2) * jv  (RT reuses X region; X is dead)
    #pragma unroll
    for (int i = 0; i < 2; ++i)
        #pragma unroll
        for (int j = 0; j < 4; ++j) {
            int col = n0w2 + j * 8 + t4 * 2;
            float bi0 = __ldg(&bi2[col]), bi1v = __ldg(&bi2[col + 1]);
            int r0 = m0w + i * 16 + g;
            float2 jv0 = __half22float2(*(__half2*)(jv + r0 * JVP + col));
            float2 jv1 = __half22float2(*(__half2*)(jv + (r0 + 8) * JVP + col));
            float g0 = 1.f / (1.f + __expf(-(O[i][j][0] + bi0)));
            float g1 = 1.f / (1.f + __expf(-(O[i][j][1] + bi1v)));
            float g2 = 1.f / (1.f + __expf(-(O[i][j][2] + bi0)));
            float g3 = 1.f / (1.f + __expf(-(O[i][j][3] + bi1v)));
            RT[r0 * RTP + col]           = g0 * jv0.x;
            RT[r0 * RTP + col + 1]       = g1 * jv0.y;
            RT[(r0 + 8) * RTP + col]     = g2 * jv1.x;
            RT[(r0 + 8) * RTP + col + 1] = g3 * jv1.y;
        }
    __syncthreads();

    // ---- segment-sum over sorted graph ids: 256 threads = 128 cols x 2 row-halves ----
    {
        const int c  = tid & 127;
        const int hf = tid >> 7;
        const int i0 = hf * 32, i1 = i0 + 32;
        float sum = 0.f;
        int gp = -1;
        #pragma unroll 4
        for (int i = i0; i < i1; ++i) {
            int gg = gsh[i];
            if (gg != gp) {
                if (gp >= 0) atomicAdd(&R[gp * GDIM + c], sum);
                sum = 0.f;
                gp = gg;
            }
            sum += RT[i * RTP + c];
        }
        if (gp >= 0) atomicAdd(&R[gp * GDIM + c], sum);
    }
}

extern "C" void kernel_launch(void* const* d_in, const int* in_sizes, int n_in,
                              void* d_out, int out_size)
{
    (void)in_sizes; (void)n_in; (void)out_size;
    const float* h_T  = (const float*)d_in[0];
    const float* h_0  = (const float*)d_in[1];
    const int*   gidx = (const int*)d_in[2];
    const float* Wi1  = (const float*)d_in[3];
    const float* bi1  = (const float*)d_in[4];
    const float* Wi2  = (const float*)d_in[5];
    const float* bi2  = (const float*)d_in[6];
    const float* Wj1  = (const float*)d_in[7];
    const float* bj1  = (const float*)d_in[8];
    const float* Wj2  = (const float*)d_in[9];
    const float* bj2  = (const float*)d_in[10];
    float* R = (float*)d_out;

    cudaFuncSetAttribute(readout_mma_kernel,
                         cudaFuncAttributeMaxDynamicSharedMemorySize, SMEM_BYTES);

    prep_w1_kernel<<<(HIDDEN * (256 + 128) + 255) / 256, 256>>>(Wi1, Wj1);
    prep_w2_kernel<<<(2 * HIDDEN * GDIM + 255) / 256, 256>>>(Wi2, Wj2);
    zero_out_kernel<<<(NGRAPH * GDIM + 255) / 256, 256>>>(R, NGRAPH * GDIM);
    readout_mma_kernel<<<NTILES, THREADS, SMEM_BYTES>>>(
        h_T, h_0, gidx, bi1, bi2, bj1, bj2, R);
}

// round 14
// speedup vs baseline: 9.1336x; 1.0504x over previous
#include <cuda_runtime.h>
#include <cuda_fp16.h>
#include <cstdint>

#define NNODE   200000
#define NDIM    128
#define HIDDEN  512
#define GDIM    128
#define NGRAPH  1024

#define TM      64
#define THREADS 256
#define NTILES  (NNODE / TM)               // 3125, exact
#define NCH     8                           // hidden chunks of 64
#define XC      6                           // X A-frag k-steps cached in regs (k < 96)

// smem pitches (half elements)
#define XP   264     // X  [64][264]
#define HP   72      // H  [64][72]
#define JVP  136     // jv [64][136] fp16
#define RTP  132     // RT [64][132] f32

// smem byte offsets
#define SX    0                        // 64*264*2 = 33792 (reused as RT: 64*132*4 = 33792)
#define SH0   33792                    // H ping   64*72*2 = 9216
#define SH1   43008                    // H pong   9216
#define SJV   52224                    // 64*136*2 = 17408
#define SG    69632                    // gsh 64 ints
#define SMEM_BYTES 69888               // x2 CTA = 139776, well under carveout

// ---- weights pre-arranged in mma B-fragment order ----
// W1 frags: [(c*4 + nw)*NKS + ks][lane] -> 4 x b32 (16B), NKS = KD/16
__device__ __align__(16) __half g_W1if[NCH * 4 * 16 * 32 * 8];   // 256 KB
__device__ __align__(16) __half g_W1jf[NCH * 4 *  8 * 32 * 8];   // 128 KB
// W2 frags: [(((c*4+ks)*4 + nw)*2 + tt)][lane] -> 4 x b32
__device__ __align__(16) __half g_W2if[NCH * 4 * 4 * 2 * 32 * 8];  // 128 KB
__device__ __align__(16) __half g_W2jf[NCH * 4 * 4 * 2 * 32 * 8];  // 128 KB

// ---------------- PTX helpers ----------------
__device__ __forceinline__ uint32_t smem_u32(const void* p) {
    uint32_t a;
    asm("{ .reg .u64 t; cvta.to.shared.u64 t, %1; cvt.u32.u64 %0, t; }" : "=r"(a) : "l"(p));
    return a;
}
__device__ __forceinline__ void ldm4(uint32_t* r, uint32_t addr) {
    asm volatile("ldmatrix.sync.aligned.m8n8.x4.shared.b16 {%0,%1,%2,%3}, [%4];"
                 : "=r"(r[0]), "=r"(r[1]), "=r"(r[2]), "=r"(r[3]) : "r"(addr));
}
__device__ __forceinline__ void mma16816(float* d, const uint32_t* a, uint32_t b0, uint32_t b1) {
    asm volatile("mma.sync.aligned.m16n8k16.row.col.f32.f16.f16.f32 "
                 "{%0,%1,%2,%3}, {%4,%5,%6,%7}, {%8,%9}, {%0,%1,%2,%3};"
                 : "+f"(d[0]), "+f"(d[1]), "+f"(d[2]), "+f"(d[3])
                 : "r"(a[0]), "r"(a[1]), "r"(a[2]), "r"(a[3]), "r"(b0), "r"(b1));
}

// ---------------- prep kernels: f32 weights -> fragment-order fp16 ----------------
// Fragment element (r, e) of lane l covers: n_off = ((r>>1)&1)*8 + (l>>2),
// k_off = (r&1)*8 + (l&3)*2 + e   (validated against the ldmatrix path in R7-R10)
__global__ void prep_w1f_kernel(const float* __restrict__ Wi1, const float* __restrict__ Wj1)
{
    int idx = blockIdx.x * blockDim.x + threadIdx.x;    // 16B chunks
    const int NI = NCH * 4 * 16 * 32;                   // 16384
    const int NJ = NCH * 4 * 8 * 32;                    // 8192
    if (idx < NI) {
        int t = idx, lane = t & 31; t >>= 5;
        int ks = t & 15; t >>= 4;
        int nw = t & 3;  int c = t >> 2;
        __half* dst = g_W1if + (size_t)idx * 8;
        #pragma unroll
        for (int r = 0; r < 4; ++r)
            #pragma unroll
            for (int e = 0; e < 2; ++e) {
                int n = c * 64 + nw * 16 + ((r >> 1) & 1) * 8 + (lane >> 2);
                int k = ks * 16 + (r & 1) * 8 + (lane & 3) * 2 + e;
                dst[r * 2 + e] = __float2half_rn(Wi1[k * HIDDEN + n]);
            }
    } else if (idx < NI + NJ) {
        int t = idx - NI, lane = t & 31; t >>= 5;
        int ks = t & 7; t >>= 3;
        int nw = t & 3;  int c = t >> 2;
        __half* dst = g_W1jf + (size_t)(idx - NI) * 8;
        #pragma unroll
        for (int r = 0; r < 4; ++r)
            #pragma unroll
            for (int e = 0; e < 2; ++e) {
                int n = c * 64 + nw * 16 + ((r >> 1) & 1) * 8 + (lane >> 2);
                int k = ks * 16 + (r & 1) * 8 + (lane & 3) * 2 + e;
                dst[r * 2 + e] = __float2half_rn(Wj1[k * HIDDEN + n]);
            }
    }
}
__global__ void prep_w2f_kernel(const float* __restrict__ Wi2, const float* __restrict__ Wj2)
{
    int idx = blockIdx.x * blockDim.x + threadIdx.x;    // 16B chunks, 8192 per net
    const int NT = NCH * 4 * 4 * 2 * 32;                // 8192
    if (idx >= 2 * NT) return;
    int net = idx >= NT;
    int t = net ? idx - NT : idx;
    int lane = t & 31; t >>= 5;
    int tt = t & 1; t >>= 1;
    int nw = t & 3; t >>= 2;
    int ks = t & 3; int c = t >> 2;
    const float* W = net ? Wj2 : Wi2;
    __half* dst = (net ? g_W2jf : g_W2if) + (size_t)(net ? idx - NT : idx) * 8;
    #pragma unroll
    for (int r = 0; r < 4; ++r)
        #pragma unroll
        for (int e = 0; e < 2; ++e) {
            int n = nw * 32 + tt * 16 + ((r >> 1) & 1) * 8 + (lane >> 2);
            int k = c * 64 + ks * 16 + (r & 1) * 8 + (lane & 3) * 2 + e;
            dst[r * 2 + e] = __float2half_rn(W[k * GDIM + n]);
        }
}

__global__ void zero_out_kernel(float* __restrict__ R, int n)
{
    int i = blockIdx.x * blockDim.x + threadIdx.x;
    if (i < n) R[i] = 0.f;
}

// ---------------- one net phase ----------------
template <int KD>
__device__ __forceinline__ void run_phase(
    const __half* __restrict__ w1f, const __half* __restrict__ w2f,
    const float* __restrict__ b1,
    uint32_t xs_u, uint32_t h_u, __half* Hs,
    const uint32_t (&xa0)[XC][4], const uint32_t (&xa1)[XC][4],
    float (&O)[2][4][4],
    int lane, int nw, int m0w, int n0w1, int n0w2, int g, int t4,
    int rowA, int colA)
{
    constexpr int NKS = KD / 16;

    #pragma unroll 1
    for (int c = 0; c < NCH; ++c) {
        const uint32_t hb_u = h_u + (uint32_t)((c & 1) * 9216);
        __half* Hb = Hs + (c & 1) * 4608;

        // ---- L1: X[64,KD] @ W1chunk -> H[64,64]; warp tile 32x16; B via LDG frags ----
        {
            const uint4* W1F = (const uint4*)w1f + ((size_t)(c * 4 + nw) * NKS) * 32 + lane;
            uint4 bp0 = W1F[0];
            uint4 bp1 = W1F[32];

            float D[2][2][4];
            #pragma unroll
            for (int i = 0; i < 2; ++i)
                #pragma unroll
                for (int j = 0; j < 2; ++j)
                    #pragma unroll
                    for (int r = 0; r < 4; ++r) D[i][j][r] = 0.f;

            #pragma unroll
            for (int ks = 0; ks < NKS; ++ks) {
                uint4 cur = (ks & 1) ? bp1 : bp0;
                if (ks + 2 < NKS) {
                    if (ks & 1) bp1 = W1F[(ks + 2) * 32];
                    else        bp0 = W1F[(ks + 2) * 32];
                }
                uint32_t t0[4], t1[4];
                if (ks >= XC) {
                    ldm4(t0, xs_u + ((m0w + rowA) * XP + ks * 16 + colA) * 2);
                    ldm4(t1, xs_u + ((m0w + 16 + rowA) * XP + ks * 16 + colA) * 2);
                }
                const uint32_t* a0 = (ks < XC) ? xa0[ks] : t0;
                const uint32_t* a1 = (ks < XC) ? xa1[ks] : t1;
                mma16816(D[0][0], a0, cur.x, cur.y);
                mma16816(D[0][1], a0, cur.z, cur.w);
                mma16816(D[1][0], a1, cur.x, cur.y);
                mma16816(D[1][1], a1, cur.z, cur.w);
            }
            // bias + ReLU -> H (fp16), ping-pong buffer
            #pragma unroll
            for (int i = 0; i < 2; ++i)
                #pragma unroll
                for (int j = 0; j < 2; ++j) {
                    int col = n0w1 + j * 8 + t4 * 2;
                    float b0v = __ldg(&b1[c * 64 + col]);
                    float b1v = __ldg(&b1[c * 64 + col + 1]);
                    int r0 = m0w + i * 16 + g;
                    float v0 = fmaxf(D[i][j][0] + b0v, 0.f);
                    float v1 = fmaxf(D[i][j][1] + b1v, 0.f);
                    float v2 = fmaxf(D[i][j][2] + b0v, 0.f);
                    float v3 = fmaxf(D[i][j][3] + b1v, 0.f);
                    *(__half2*)(Hb + r0 * HP + col)       = __floats2half2_rn(v0, v1);
                    *(__half2*)(Hb + (r0 + 8) * HP + col) = __floats2half2_rn(v2, v3);
                }
        }
        __syncthreads();   // H visible; only barrier per chunk

        // ---- L2: O += H[64,64] @ W2chunk[64,128]; warp tile 32x32; B via LDG frags ----
        {
            const uint4* W2F = (const uint4*)w2f;
            #define W2IDX(KS, TT) (((size_t)(((c * 4 + (KS)) * 4 + nw) * 2 + (TT))) * 32 + lane)
            uint4 q00 = W2F[W2IDX(0, 0)], q01 = W2F[W2IDX(0, 1)];
            uint4 q10 = W2F[W2IDX(1, 0)], q11 = W2F[W2IDX(1, 1)];

            #pragma unroll
            for (int ks = 0; ks < 4; ++ks) {
                uint4 cur0 = (ks & 1) ? q10 : q00;
                uint4 cur1 = (ks & 1) ? q11 : q01;
                if (ks + 2 < 4) {
                    if (ks & 1) { q10 = W2F[W2IDX(ks + 2, 0)]; q11 = W2F[W2IDX(ks + 2, 1)]; }
                    else        { q00 = W2F[W2IDX(ks + 2, 0)]; q01 = W2F[W2IDX(ks + 2, 1)]; }
                }
                uint32_t a0[4], a1[4];
                ldm4(a0, hb_u + ((m0w + rowA) * HP + ks * 16 + colA) * 2);
                ldm4(a1, hb_u + ((m0w + 16 + rowA) * HP + ks * 16 + colA) * 2);
                mma16816(O[0][0], a0, cur0.x, cur0.y);
                mma16816(O[0][1], a0, cur0.z, cur0.w);
                mma16816(O[1][0], a1, cur0.x, cur0.y);
                mma16816(O[1][1], a1, cur0.z, cur0.w);
                mma16816(O[0][2], a0, cur1.x, cur1.y);
                mma16816(O[0][3], a0, cur1.z, cur1.w);
                mma16816(O[1][2], a1, cur1.x, cur1.y);
                mma16816(O[1][3], a1, cur1.z, cur1.w);
            }
            #undef W2IDX
        }
        // no trailing barrier: next chunk's L1 writes the other H buffer
    }
}

// ---------------- main kernel ----------------
__global__ __launch_bounds__(THREADS, 2)
void readout_mma_kernel(
    const float* __restrict__ h_T, const float* __restrict__ h_0,
    const int* __restrict__ graph_index,
    const float* __restrict__ bi1, const float* __restrict__ bi2,
    const float* __restrict__ bj1, const float* __restrict__ bj2,
    float* __restrict__ R)
{
    extern __shared__ __align__(16) char sm[];
    __half* Xs  = (__half*)(sm + SX);
    __half* Hs  = (__half*)(sm + SH0);
    __half* jv  = (__half*)(sm + SJV);
    int*    gsh = (int*)(sm + SG);
    float*  RT  = (float*)(sm + SX);

    const int tid  = threadIdx.x;
    const int wid  = tid >> 5;
    const int lane = tid & 31;
    const int g    = lane >> 2;
    const int t4   = lane & 3;
    const int mw   = wid & 1;         // M-split (2)
    const int nw   = wid >> 1;        // N-split (4)
    const int m0w  = mw * 32;

    const int lr = lane & 7, lm = lane >> 3;
    const int rowA = lr + (lm & 1) * 8, colA = (lm >> 1) * 8;   // A (row-major [m][k])

    const uint32_t xs_u = smem_u32(sm + SX);
    const uint32_t h_u  = smem_u32(sm + SH0);

    const int m0 = blockIdx.x * TM;

    if (tid < TM) {
        int gg = graph_index[m0 + tid];
        gsh[tid] = gg < 0 ? 0 : (gg >= NGRAPH ? NGRAPH - 1 : gg);
    }

    // stage X: [node][k] fp16, k = h_T(0..127) || h_0(128..255); 4 threads/row
    {
        int nl = tid >> 2, seg = tid & 3;
        const float* base = (seg < 2) ? h_T : h_0;
        const float4* src = (const float4*)(base + (size_t)(m0 + nl) * NDIM + (seg & 1) * 64);
        __half2* dst = (__half2*)(Xs + nl * XP + seg * 64);
        #pragma unroll 8
        for (int q = 0; q < 16; ++q) {
            float4 f = src[q];
            dst[q * 2]     = __floats2half2_rn(f.x, f.y);
            dst[q * 2 + 1] = __floats2half2_rn(f.z, f.w);
        }
    }
    __syncthreads();

    // cache X A-fragments for k < 16*XC (invariant across chunks/phases)
    uint32_t xa0[XC][4], xa1[XC][4];
    #pragma unroll
    for (int ks = 0; ks < XC; ++ks) {
        ldm4(xa0[ks], xs_u + ((m0w + rowA) * XP + ks * 16 + colA) * 2);
        ldm4(xa1[ks], xs_u + ((m0w + 16 + rowA) * XP + ks * 16 + colA) * 2);
    }

    const int n0w1 = nw * 16;
    const int n0w2 = nw * 32;

    float O[2][4][4];

    // ================= phase 1: j-net (K = 128) =================
    #pragma unroll
    for (int i = 0; i < 2; ++i)
        #pragma unroll
        for (int j = 0; j < 4; ++j)
            #pragma unroll
            for (int r = 0; r < 4; ++r) O[i][j][r] = 0.f;

    run_phase<NDIM>(g_W1jf, g_W2jf, bj1, xs_u, h_u, Hs, xa0, xa1, O,
                    lane, nw, m0w, n0w1, n0w2, g, t4, rowA, colA);

    // j epilogue: jv = O + bj2 (fp16)
    #pragma unroll
    for (int i = 0; i < 2; ++i)
        #pragma unroll
        for (int j = 0; j < 4; ++j) {
            int col = n0w2 + j * 8 + t4 * 2;
            float bj0 = __ldg(&bj2[col]), bj1v = __ldg(&bj2[col + 1]);
            int r0 = m0w + i * 16 + g;
            *(__half2*)(jv + r0 * JVP + col) =
                __floats2half2_rn(O[i][j][0] + bj0, O[i][j][1] + bj1v);
            *(__half2*)(jv + (r0 + 8) * JVP + col) =
                __floats2half2_rn(O[i][j][2] + bj0, O[i][j][3] + bj1v);
        }

    // ================= phase 2: i-net (K = 256) =================
    #pragma unroll
    for (int i = 0; i < 2; ++i)
        #pragma unroll
        for (int j = 0; j < 4; ++j)
            #pragma unroll
            for (int r = 0; r < 4; ++r) O[i][j][r] = 0.f;

    run_phase<2 * NDIM>(g_W1if, g_W2if, bi1, xs_u, h_u, Hs, xa0, xa1, O,
                        lane, nw, m0w, n0w1, n0w2, g, t4, rowA, colA);

    // i epilogue: RT = sigmoid(O + bi2) * jv  (RT reuses X region; X is dead)
    #pragma unroll
    for (int i = 0; i < 2; ++i)
        #pragma unroll
        for (int j = 0; j < 4; ++j) {
            int col = n0w2 + j * 8 + t4 * 2;
            float bi0 = __ldg(&bi2[col]), bi1v = __ldg(&bi2[col + 1]);
            int r0 = m0w + i * 16 + g;
            float2 jv0 = __half22float2(*(__half2*)(jv + r0 * JVP + col));
            float2 jv1 = __half22float2(*(__half2*)(jv + (r0 + 8) * JVP + col));
            float g0 = 1.f / (1.f + __expf(-(O[i][j][0] + bi0)));
            float g1 = 1.f / (1.f + __expf(-(O[i][j][1] + bi1v)));
            float g2 = 1.f / (1.f + __expf(-(O[i][j][2] + bi0)));
            float g3 = 1.f / (1.f + __expf(-(O[i][j][3] + bi1v)));
            RT[r0 * RTP + col]           = g0 * jv0.x;
            RT[r0 * RTP + col + 1]       = g1 * jv0.y;
            RT[(r0 + 8) * RTP + col]     = g2 * jv1.x;
            RT[(r0 + 8) * RTP + col + 1] = g3 * jv1.y;
        }
    __syncthreads();

    // ---- segment-sum over sorted graph ids: 256 threads = 128 cols x 2 row-halves ----
    {
        const int c  = tid & 127;
        const int hf = tid >> 7;
        const int i0 = hf * 32, i1 = i0 + 32;
        float sum = 0.f;
        int gp = -1;
        #pragma unroll 4
        for (int i = i0; i < i1; ++i) {
            int gg = gsh[i];
            if (gg != gp) {
                if (gp >= 0) atomicAdd(&R[gp * GDIM + c], sum);
                sum = 0.f;
                gp = gg;
            }
            sum += RT[i * RTP + c];
        }
        if (gp >= 0) atomicAdd(&R[gp * GDIM + c], sum);
    }
}

extern "C" void kernel_launch(void* const* d_in, const int* in_sizes, int n_in,
                              void* d_out, int out_size)
{
    (void)in_sizes; (void)n_in; (void)out_size;
    const float* h_T  = (const float*)d_in[0];
    const float* h_0  = (const float*)d_in[1];
    const int*   gidx = (const int*)d_in[2];
    const float* Wi1  = (const float*)d_in[3];
    const float* bi1  = (const float*)d_in[4];
    const float* Wi2  = (const float*)d_in[5];
    const float* bi2  = (const float*)d_in[6];
    const float* Wj1  = (const float*)d_in[7];
    const float* bj1  = (const float*)d_in[8];
    const float* Wj2  = (const float*)d_in[9];
    const float* bj2  = (const float*)d_in[10];
    float* R = (float*)d_out;

    cudaFuncSetAttribute(readout_mma_kernel,
                         cudaFuncAttributeMaxDynamicSharedMemorySize, SMEM_BYTES);

    prep_w1f_kernel<<<(NCH * 4 * (16 + 8) * 32 + 255) / 256, 256>>>(Wi1, Wj1);
    prep_w2f_kernel<<<(2 * NCH * 4 * 4 * 2 * 32 + 255) / 256, 256>>>(Wi2, Wj2);
    zero_out_kernel<<<(NGRAPH * GDIM + 255) / 256, 256>>>(R, NGRAPH * GDIM);
    readout_mma_kernel<<<NTILES, THREADS, SMEM_BYTES>>>(
        h_T, h_0, gidx, bi1, bi2, bj1, bj2, R);
}

// round 16
// speedup vs baseline: 9.6172x; 1.0530x over previous
#include <cuda_runtime.h>
#include <cuda_fp16.h>
#include <cstdint>

#define NNODE   200000
#define NDIM    128
#define HIDDEN  512
#define GDIM    128
#define NGRAPH  1024

#define TM      64
#define THREADS 256
#define NTILES  (NNODE / TM)               // 3125, exact
#define NCH     8                           // hidden chunks of 64
#define XC      4                           // X A-frag k-steps cached in regs (k < 64)

// smem pitches (half elements)
#define XP   264     // X  [64][264]
#define HP   72      // H  [64][72]
#define JVP  136     // jv [64][136] fp16
#define RTP  132     // RT [64][132] f32

// smem byte offsets
#define SX    0                        // 64*264*2 = 33792 (reused as RT: 64*132*4 = 33792)
#define SH0   33792                    // H ping   64*72*2 = 9216
#define SH1   43008                    // H pong   9216
#define SJV   52224                    // 64*136*2 = 17408
#define SG    69632                    // gsh 64 ints
#define SMEM_BYTES 69888               // x2 CTA = 139776, well under carveout

// ---- weights pre-arranged in mma B-fragment order ----
// W1 frags: [(c*4 + nw)*NKS + ks][lane] -> 4 x b32 (16B), NKS = KD/16
__device__ __align__(16) __half g_W1if[NCH * 4 * 16 * 32 * 8];   // 256 KB
__device__ __align__(16) __half g_W1jf[NCH * 4 *  8 * 32 * 8];   // 128 KB
// W2 frags: [(((c*4+ks)*4 + nw)*2 + tt)][lane] -> 4 x b32
__device__ __align__(16) __half g_W2if[NCH * 4 * 4 * 2 * 32 * 8];  // 128 KB
__device__ __align__(16) __half g_W2jf[NCH * 4 * 4 * 2 * 32 * 8];  // 128 KB

// ---------------- PTX helpers ----------------
__device__ __forceinline__ uint32_t smem_u32(const void* p) {
    uint32_t a;
    asm("{ .reg .u64 t; cvta.to.shared.u64 t, %1; cvt.u32.u64 %0, t; }" : "=r"(a) : "l"(p));
    return a;
}
__device__ __forceinline__ void ldm4(uint32_t* r, uint32_t addr) {
    asm volatile("ldmatrix.sync.aligned.m8n8.x4.shared.b16 {%0,%1,%2,%3}, [%4];"
                 : "=r"(r[0]), "=r"(r[1]), "=r"(r[2]), "=r"(r[3]) : "r"(addr));
}
__device__ __forceinline__ void mma16816(float* d, const uint32_t* a, uint32_t b0, uint32_t b1) {
    asm volatile("mma.sync.aligned.m16n8k16.row.col.f32.f16.f16.f32 "
                 "{%0,%1,%2,%3}, {%4,%5,%6,%7}, {%8,%9}, {%0,%1,%2,%3};"
                 : "+f"(d[0]), "+f"(d[1]), "+f"(d[2]), "+f"(d[3])
                 : "r"(a[0]), "r"(a[1]), "r"(a[2]), "r"(a[3]), "r"(b0), "r"(b1));
}
__device__ __forceinline__ size_t w2idx(int c, int ks, int tt, int nw, int lane) {
    return ((size_t)(((c * 4 + ks) * 4 + nw) * 2 + tt)) * 32 + lane;
}

// ---------------- prep kernels: f32 weights -> fragment-order fp16 ----------------
// Fragment element (r, e) of lane l covers: n_off = ((r>>1)&1)*8 + (l>>2),
// k_off = (r&1)*8 + (l&3)*2 + e
__global__ void prep_w1f_kernel(const float* __restrict__ Wi1, const float* __restrict__ Wj1)
{
    int idx = blockIdx.x * blockDim.x + threadIdx.x;    // 16B chunks
    const int NI = NCH * 4 * 16 * 32;                   // 16384
    const int NJ = NCH * 4 * 8 * 32;                    // 8192
    if (idx < NI) {
        int t = idx, lane = t & 31; t >>= 5;
        int ks = t & 15; t >>= 4;
        int nw = t & 3;  int c = t >> 2;
        __half* dst = g_W1if + (size_t)idx * 8;
        #pragma unroll
        for (int r = 0; r < 4; ++r)
            #pragma unroll
            for (int e = 0; e < 2; ++e) {
                int n = c * 64 + nw * 16 + ((r >> 1) & 1) * 8 + (lane >> 2);
                int k = ks * 16 + (r & 1) * 8 + (lane & 3) * 2 + e;
                dst[r * 2 + e] = __float2half_rn(Wi1[k * HIDDEN + n]);
            }
    } else if (idx < NI + NJ) {
        int t = idx - NI, lane = t & 31; t >>= 5;
        int ks = t & 7; t >>= 3;
        int nw = t & 3;  int c = t >> 2;
        __half* dst = g_W1jf + (size_t)(idx - NI) * 8;
        #pragma unroll
        for (int r = 0; r < 4; ++r)
            #pragma unroll
            for (int e = 0; e < 2; ++e) {
                int n = c * 64 + nw * 16 + ((r >> 1) & 1) * 8 + (lane >> 2);
                int k = ks * 16 + (r & 1) * 8 + (lane & 3) * 2 + e;
                dst[r * 2 + e] = __float2half_rn(Wj1[k * HIDDEN + n]);
            }
    }
}
__global__ void prep_w2f_kernel(const float* __restrict__ Wi2, const float* __restrict__ Wj2)
{
    int idx = blockIdx.x * blockDim.x + threadIdx.x;    // 16B chunks, 8192 per net
    const int NT = NCH * 4 * 4 * 2 * 32;                // 8192
    if (idx >= 2 * NT) return;
    int net = idx >= NT;
    int t = net ? idx - NT : idx;
    int lane = t & 31; t >>= 5;
    int tt = t & 1; t >>= 1;
    int nw = t & 3; t >>= 2;
    int ks = t & 3; int c = t >> 2;
    const float* W = net ? Wj2 : Wi2;
    __half* dst = (net ? g_W2jf : g_W2if) + (size_t)(net ? idx - NT : idx) * 8;
    #pragma unroll
    for (int r = 0; r < 4; ++r)
        #pragma unroll
        for (int e = 0; e < 2; ++e) {
            int n = nw * 32 + tt * 16 + ((r >> 1) & 1) * 8 + (lane >> 2);
            int k = c * 64 + ks * 16 + (r & 1) * 8 + (lane & 3) * 2 + e;
            dst[r * 2 + e] = __float2half_rn(W[k * GDIM + n]);
        }
}

__global__ void zero_out_kernel(float* __restrict__ R, int n)
{
    int i = blockIdx.x * blockDim.x + threadIdx.x;
    if (i < n) R[i] = 0.f;
}

// ---------------- one pipelined chunk: L1(c) interleaved with L2(c-1) ----------------
template <int KD, bool DO_L2>
__device__ __forceinline__ void chunk_step(
    int c,
    const __half* __restrict__ w1f, const uint4* __restrict__ W2F,
    const float* __restrict__ b1,
    uint32_t xs_u, uint32_t h_u, __half* Hs,
    const uint32_t (&xa0)[XC][4], const uint32_t (&xa1)[XC][4],
    float (&O)[2][4][4],
    int lane, int nw, int m0w, int n0w1, int g, int t4,
    int rowA, int colA)
{
    constexpr int NKS = KD / 16;
    constexpr int GAP = NKS / 4;     // one L2 step per GAP L1 steps

    const uint4* W1F = (const uint4*)w1f + ((size_t)(c * 4 + nw) * NKS) * 32 + lane;
    uint4 bp0 = W1F[0];
    uint4 bp1 = W1F[32];

    const int c2 = c - 1;
    const uint32_t hb_u = h_u + (uint32_t)((c2 & 1) * 9216);
    uint4 qa0, qa1, qb0, qb1;
    if (DO_L2) {
        qa0 = W2F[w2idx(c2, 0, 0, nw, lane)]; qa1 = W2F[w2idx(c2, 0, 1, nw, lane)];
        qb0 = W2F[w2idx(c2, 1, 0, nw, lane)]; qb1 = W2F[w2idx(c2, 1, 1, nw, lane)];
    }

    float D[2][2][4];
    #pragma unroll
    for (int i = 0; i < 2; ++i)
        #pragma unroll
        for (int j = 0; j < 2; ++j)
            #pragma unroll
            for (int r = 0; r < 4; ++r) D[i][j][r] = 0.f;

    #pragma unroll
    for (int ks = 0; ks < NKS; ++ks) {
        // ---- L1 step ks ----
        uint4 cur = (ks & 1) ? bp1 : bp0;
        if (ks + 2 < NKS) {
            if (ks & 1) bp1 = W1F[(ks + 2) * 32];
            else        bp0 = W1F[(ks + 2) * 32];
        }
        uint32_t t0[4], t1[4];
        if (ks >= XC) {
            ldm4(t0, xs_u + ((m0w + rowA) * XP + ks * 16 + colA) * 2);
            ldm4(t1, xs_u + ((m0w + 16 + rowA) * XP + ks * 16 + colA) * 2);
        }
        const uint32_t* a0 = (ks < XC) ? xa0[ks] : t0;
        const uint32_t* a1 = (ks < XC) ? xa1[ks] : t1;
        mma16816(D[0][0], a0, cur.x, cur.y);
        mma16816(D[0][1], a0, cur.z, cur.w);
        mma16816(D[1][0], a1, cur.x, cur.y);
        mma16816(D[1][1], a1, cur.z, cur.w);

        // ---- interleaved L2 step (consumes H[c-1]) ----
        if (DO_L2 && ((ks % GAP) == GAP - 1)) {
            const int k2 = ks / GAP;
            uint4 cur0 = (k2 & 1) ? qb0 : qa0;
            uint4 cur1 = (k2 & 1) ? qb1 : qa1;
            if (k2 + 2 < 4) {
                if (k2 & 1) { qb0 = W2F[w2idx(c2, k2 + 2, 0, nw, lane)];
                              qb1 = W2F[w2idx(c2, k2 + 2, 1, nw, lane)]; }
                else        { qa0 = W2F[w2idx(c2, k2 + 2, 0, nw, lane)];
                              qa1 = W2F[w2idx(c2, k2 + 2, 1, nw, lane)]; }
            }
            uint32_t ha0[4], ha1[4];
            ldm4(ha0, hb_u + ((m0w + rowA) * HP + k2 * 16 + colA) * 2);
            ldm4(ha1, hb_u + ((m0w + 16 + rowA) * HP + k2 * 16 + colA) * 2);
            mma16816(O[0][0], ha0, cur0.x, cur0.y);
            mma16816(O[0][1], ha0, cur0.z, cur0.w);
            mma16816(O[1][0], ha1, cur0.x, cur0.y);
            mma16816(O[1][1], ha1, cur0.z, cur0.w);
            mma16816(O[0][2], ha0, cur1.x, cur1.y);
            mma16816(O[0][3], ha0, cur1.z, cur1.w);
            mma16816(O[1][2], ha1, cur1.x, cur1.y);
            mma16816(O[1][3], ha1, cur1.z, cur1.w);
        }
    }

    // ---- epilogue: bias + ReLU -> H[c&1] (fp16) ----
    __half* Hb = Hs + (c & 1) * 4608;
    #pragma unroll
    for (int i = 0; i < 2; ++i)
        #pragma unroll
        for (int j = 0; j < 2; ++j) {
            int col = n0w1 + j * 8 + t4 * 2;
            float b0v = __ldg(&b1[c * 64 + col]);
            float b1v = __ldg(&b1[c * 64 + col + 1]);
            int r0 = m0w + i * 16 + g;
            float v0 = fmaxf(D[i][j][0] + b0v, 0.f);
            float v1 = fmaxf(D[i][j][1] + b1v, 0.f);
            float v2 = fmaxf(D[i][j][2] + b0v, 0.f);
            float v3 = fmaxf(D[i][j][3] + b1v, 0.f);
            *(__half2*)(Hb + r0 * HP + col)       = __floats2half2_rn(v0, v1);
            *(__half2*)(Hb + (r0 + 8) * HP + col) = __floats2half2_rn(v2, v3);
        }
    __syncthreads();   // single barrier per chunk
}

// ---------------- one net phase ----------------
template <int KD>
__device__ __forceinline__ void run_phase(
    const __half* __restrict__ w1f, const __half* __restrict__ w2f,
    const float* __restrict__ b1,
    uint32_t xs_u, uint32_t h_u, __half* Hs,
    const uint32_t (&xa0)[XC][4], const uint32_t (&xa1)[XC][4],
    float (&O)[2][4][4],
    int lane, int nw, int m0w, int n0w1, int g, int t4,
    int rowA, int colA)
{
    const uint4* W2F = (const uint4*)w2f;

    chunk_step<KD, false>(0, w1f, W2F, b1, xs_u, h_u, Hs, xa0, xa1, O,
                          lane, nw, m0w, n0w1, g, t4, rowA, colA);
    #pragma unroll 1
    for (int c = 1; c < NCH; ++c)
        chunk_step<KD, true>(c, w1f, W2F, b1, xs_u, h_u, Hs, xa0, xa1, O,
                             lane, nw, m0w, n0w1, g, t4, rowA, colA);

    // tail: L2 for chunk NCH-1
    {
        const int c2 = NCH - 1;
        const uint32_t hb_u = h_u + (uint32_t)((c2 & 1) * 9216);
        #pragma unroll
        for (int k2 = 0; k2 < 4; ++k2) {
            uint4 cur0 = W2F[w2idx(c2, k2, 0, nw, lane)];
            uint4 cur1 = W2F[w2idx(c2, k2, 1, nw, lane)];
            uint32_t ha0[4], ha1[4];
            ldm4(ha0, hb_u + ((m0w + rowA) * HP + k2 * 16 + colA) * 2);
            ldm4(ha1, hb_u + ((m0w + 16 + rowA) * HP + k2 * 16 + colA) * 2);
            mma16816(O[0][0], ha0, cur0.x, cur0.y);
            mma16816(O[0][1], ha0, cur0.z, cur0.w);
            mma16816(O[1][0], ha1, cur0.x, cur0.y);
            mma16816(O[1][1], ha1, cur0.z, cur0.w);
            mma16816(O[0][2], ha0, cur1.x, cur1.y);
            mma16816(O[0][3], ha0, cur1.z, cur1.w);
            mma16816(O[1][2], ha1, cur1.x, cur1.y);
            mma16816(O[1][3], ha1, cur1.z, cur1.w);
        }
    }
}

// ---------------- main kernel ----------------
__global__ __launch_bounds__(THREADS, 2)
void readout_mma_kernel(
    const float* __restrict__ h_T, const float* __restrict__ h_0,
    const int* __restrict__ graph_index,
    const float* __restrict__ bi1, const float* __restrict__ bi2,
    const float* __restrict__ bj1, const float* __restrict__ bj2,
    float* __restrict__ R)
{
    extern __shared__ __align__(16) char sm[];
    __half* Xs  = (__half*)(sm + SX);
    __half* Hs  = (__half*)(sm + SH0);
    __half* jv  = (__half*)(sm + SJV);
    int*    gsh = (int*)(sm + SG);
    float*  RT  = (float*)(sm + SX);

    const int tid  = threadIdx.x;
    const int wid  = tid >> 5;
    const int lane = tid & 31;
    const int g    = lane >> 2;
    const int t4   = lane & 3;
    const int mw   = wid & 1;         // M-split (2)
    const int nw   = wid >> 1;        // N-split (4)
    const int m0w  = mw * 32;

    const int lr = lane & 7, lm = lane >> 3;
    const int rowA = lr + (lm & 1) * 8, colA = (lm >> 1) * 8;   // A (row-major [m][k])

    const uint32_t xs_u = smem_u32(sm + SX);
    const uint32_t h_u  = smem_u32(sm + SH0);

    const int m0 = blockIdx.x * TM;

    if (tid < TM) {
        int gg = graph_index[m0 + tid];
        gsh[tid] = gg < 0 ? 0 : (gg >= NGRAPH ? NGRAPH - 1 : gg);
    }

    // stage X: [node][k] fp16, k = h_T(0..127) || h_0(128..255); 4 threads/row
    {
        int nl = tid >> 2, seg = tid & 3;
        const float* base = (seg < 2) ? h_T : h_0;
        const float4* src = (const float4*)(base + (size_t)(m0 + nl) * NDIM + (seg & 1) * 64);
        __half2* dst = (__half2*)(Xs + nl * XP + seg * 64);
        #pragma unroll 8
        for (int q = 0; q < 16; ++q) {
            float4 f = src[q];
            dst[q * 2]     = __floats2half2_rn(f.x, f.y);
            dst[q * 2 + 1] = __floats2half2_rn(f.z, f.w);
        }
    }
    __syncthreads();

    // cache X A-fragments for k < 16*XC (invariant across chunks/phases)
    uint32_t xa0[XC][4], xa1[XC][4];
    #pragma unroll
    for (int ks = 0; ks < XC; ++ks) {
        ldm4(xa0[ks], xs_u + ((m0w + rowA) * XP + ks * 16 + colA) * 2);
        ldm4(xa1[ks], xs_u + ((m0w + 16 + rowA) * XP + ks * 16 + colA) * 2);
    }

    const int n0w1 = nw * 16;
    const int n0w2 = nw * 32;

    float O[2][4][4];

    // ================= phase 1: j-net (K = 128) =================
    #pragma unroll
    for (int i = 0; i < 2; ++i)
        #pragma unroll
        for (int j = 0; j < 4; ++j)
            #pragma unroll
            for (int r = 0; r < 4; ++r) O[i][j][r] = 0.f;

    run_phase<NDIM>(g_W1jf, g_W2jf, bj1, xs_u, h_u, Hs, xa0, xa1, O,
                    lane, nw, m0w, n0w1, g, t4, rowA, colA);

    // j epilogue: jv = O + bj2 (fp16)
    #pragma unroll
    for (int i = 0; i < 2; ++i)
        #pragma unroll
        for (int j = 0; j < 4; ++j) {
            int col = n0w2 + j * 8 + t4 * 2;
            float bj0 = __ldg(&bj2[col]), bj1v = __ldg(&bj2[col + 1]);
            int r0 = m0w + i * 16 + g;
            *(__half2*)(jv + r0 * JVP + col) =
                __floats2half2_rn(O[i][j][0] + bj0, O[i][j][1] + bj1v);
            *(__half2*)(jv + (r0 + 8) * JVP + col) =
                __floats2half2_rn(O[i][j][2] + bj0, O[i][j][3] + bj1v);
        }

    // ================= phase 2: i-net (K = 256) =================
    #pragma unroll
    for (int i = 0; i < 2; ++i)
        #pragma unroll
        for (int j = 0; j < 4; ++j)
            #pragma unroll
            for (int r = 0; r < 4; ++r) O[i][j][r] = 0.f;

    run_phase<2 * NDIM>(g_W1if, g_W2if, bi1, xs_u, h_u, Hs, xa0, xa1, O,
                        lane, nw, m0w, n0w1, g, t4, rowA, colA);

    // i epilogue: RT = sigmoid(O + bi2) * jv  (RT reuses X region; X is dead)
    #pragma unroll
    for (int i = 0; i < 2; ++i)
        #pragma unroll
        for (int j = 0; j < 4; ++j) {
            int col = n0w2 + j * 8 + t4 * 2;
            float bi0 = __ldg(&bi2[col]), bi1v = __ldg(&bi2[col + 1]);
            int r0 = m0w + i * 16 + g;
            float2 jv0 = __half22float2(*(__half2*)(jv + r0 * JVP + col));
            float2 jv1 = __half22float2(*(__half2*)(jv + (r0 + 8) * JVP + col));
            float g0 = 1.f / (1.f + __expf(-(O[i][j][0] + bi0)));
            float g1 = 1.f / (1.f + __expf(-(O[i][j][1] + bi1v)));
            float g2 = 1.f / (1.f + __expf(-(O[i][j][2] + bi0)));
            float g3 = 1.f / (1.f + __expf(-(O[i][j][3] + bi1v)));
            RT[r0 * RTP + col]           = g0 * jv0.x;
            RT[r0 * RTP + col + 1]       = g1 * jv0.y;
            RT[(r0 + 8) * RTP + col]     = g2 * jv1.x;
            RT[(r0 + 8) * RTP + col + 1] = g3 * jv1.y;
        }
    __syncthreads();

    // ---- segment-sum over sorted graph ids: 256 threads = 128 cols x 2 row-halves ----
    {
        const int c  = tid & 127;
        const int hf = tid >> 7;
        const int i0 = hf * 32, i1 = i0 + 32;
        float sum = 0.f;
        int gp = -1;
        #pragma unroll 4
        for (int i = i0; i < i1; ++i) {
            int gg = gsh[i];
            if (gg != gp) {
                if (gp >= 0) atomicAdd(&R[gp * GDIM + c], sum);
                sum = 0.f;
                gp = gg;
            }
            sum += RT[i * RTP + c];
        }
        if (gp >= 0) atomicAdd(&R[gp * GDIM + c], sum);
    }
}

extern "C" void kernel_launch(void* const* d_in, const int* in_sizes, int n_in,
                              void* d_out, int out_size)
{
    (void)in_sizes; (void)n_in; (void)out_size;
    const float* h_T  = (const float*)d_in[0];
    const float* h_0  = (const float*)d_in[1];
    const int*   gidx = (const int*)d_in[2];
    const float* Wi1  = (const float*)d_in[3];
    const float* bi1  = (const float*)d_in[4];
    const float* Wi2  = (const float*)d_in[5];
    const float* bi2  = (const float*)d_in[6];
    const float* Wj1  = (const float*)d_in[7];
    const float* bj1  = (const float*)d_in[8];
    const float* Wj2  = (const float*)d_in[9];
    const float* bj2  = (const float*)d_in[10];
    float* R = (float*)d_out;

    cudaFuncSetAttribute(readout_mma_kernel,
                         cudaFuncAttributeMaxDynamicSharedMemorySize, SMEM_BYTES);

    prep_w1f_kernel<<<(NCH * 4 * (16 + 8) * 32 + 255) / 256, 256>>>(Wi1, Wj1);
    prep_w2f_kernel<<<(2 * NCH * 4 * 4 * 2 * 32 + 255) / 256, 256>>>(Wi2, Wj2);
    zero_out_kernel<<<(NGRAPH * GDIM + 255) / 256, 256>>>(R, NGRAPH * GDIM);
    readout_mma_kernel<<<NTILES, THREADS, SMEM_BYTES>>>(
        h_T, h_0, gidx, bi1, bi2, bj1, bj2, R);
}